// round 9
// baseline (speedup 1.0000x reference)
#include <cuda_runtime.h>
#include <cuda_bf16.h>
#include <stdint.h>
#include <math.h>

#define N_IMG 512
#define NCLS  100000

// ---------------- scratch (static device globals; no allocation) ----------------
__device__ float g_y1[512 * 16 * 56 * 56];
__device__ float g_y2[512 * 32 * 28 * 28];
__device__ float g_y3[512 * 64 * 26 * 26];
__device__ float g_y4[512 * 128 * 24 * 24];
__device__ float g_f32[512 * 128];
__device__ __nv_bfloat16 g_fhi[512 * 128];
__device__ __nv_bfloat16 g_flo[512 * 128];
__device__ __nv_bfloat16 g_whi[100000 * 128];
__device__ __nv_bfloat16 g_wlo[100000 * 128];
__device__ __nv_bfloat16 g_wt3h[9 * 64 * 32];
__device__ __nv_bfloat16 g_wt3l[9 * 64 * 32];
__device__ __nv_bfloat16 g_wt4h[9 * 128 * 64];
__device__ __nv_bfloat16 g_wt4l[9 * 128 * 64];
__device__ float g_part[128 * 64 * 2];
__device__ float g_bns[4 * 128];
__device__ float g_bnsh[4 * 128];

// ---------------- packed f32x2 helpers ----------------
__device__ __forceinline__ unsigned long long pack_dup(float x) {
    unsigned long long r; asm("mov.b64 %0,{%1,%1};" : "=l"(r) : "f"(x)); return r;
}
__device__ __forceinline__ unsigned long long pack2(float x, float y) {
    unsigned long long r; asm("mov.b64 %0,{%1,%2};" : "=l"(r) : "f"(x), "f"(y)); return r;
}
__device__ __forceinline__ unsigned long long ffma2(unsigned long long a, unsigned long long b,
                                                    unsigned long long c) {
    unsigned long long d;
    asm("fma.rn.f32x2 %0,%1,%2,%3;" : "=l"(d) : "l"(a), "l"(b), "l"(c));
    return d;
}
__device__ __forceinline__ float2 unpack2(unsigned long long v) {
    float2 f; asm("mov.b64 {%0,%1},%2;" : "=f"(f.x), "=f"(f.y) : "l"(v)); return f;
}

// ---------------- warp-mma helpers ----------------
__device__ __forceinline__ uint32_t smem_u32(const void* p) {
    uint32_t a;
    asm("{ .reg .u64 t; cvta.to.shared.u64 t, %1; cvt.u32.u64 %0, t; }" : "=r"(a) : "l"(p));
    return a;
}
__device__ __forceinline__ void ldsm4(uint32_t* r, uint32_t a) {
    asm volatile("ldmatrix.sync.aligned.m8n8.x4.shared.b16 {%0,%1,%2,%3}, [%4];"
                 : "=r"(r[0]), "=r"(r[1]), "=r"(r[2]), "=r"(r[3]) : "r"(a));
}
__device__ __forceinline__ void mma16816(float* c, const uint32_t* a, uint32_t b0, uint32_t b1) {
    asm volatile(
        "mma.sync.aligned.m16n8k16.row.col.f32.bf16.bf16.f32 "
        "{%0,%1,%2,%3}, {%4,%5,%6,%7}, {%8,%9}, {%0,%1,%2,%3};"
        : "+f"(c[0]), "+f"(c[1]), "+f"(c[2]), "+f"(c[3])
        : "r"(a[0]), "r"(a[1]), "r"(a[2]), "r"(a[3]), "r"(b0), "r"(b1));
}

// ---------------- direct conv (conv1 / conv2 only) ----------------
template <int CIN, int COUT, int COUTB, int KH, int KW, int STR, int PAD,
          int IH, int IW, int OH, int OW, bool INBN>
__global__ void __launch_bounds__(256, 2) conv_fwd(
    const float* __restrict__ in, const float* __restrict__ wgl,
    const float* __restrict__ bias,
    const float* __restrict__ isc, const float* __restrict__ ish,
    float* __restrict__ out)
{
    constexpr int TAPS  = KH * KW;
    constexpr int NPAIR = COUTB / 2;
    constexpr int PW    = KW + STR;
    constexpr int PPR   = OW / 2;
    constexpr int NPX   = OH * PPR;

    __shared__ __align__(16) float wsm[CIN * TAPS * COUTB];
    __shared__ float bsm[COUTB];
    __shared__ float scsm[CIN], shsm[CIN];

    const int tid = threadIdx.x;
    const int cg  = blockIdx.y;

    for (int i = tid; i < CIN * TAPS * COUTB; i += 256) {
        int co  = i % COUTB;
        int tap = (i / COUTB) % TAPS;
        int ci  = i / (COUTB * TAPS);
        wsm[i] = wgl[((cg * COUTB + co) * CIN + ci) * TAPS + tap];
    }
    if (tid < COUTB) bsm[tid] = bias[cg * COUTB + tid];
    if (INBN) {
        for (int i = tid; i < CIN; i += 256) { scsm[i] = isc[i]; shsm[i] = ish[i]; }
    }
    __syncthreads();

    const int gid = blockIdx.x * 256 + tid;
    if (gid >= N_IMG * NPX) return;
    const int n   = gid / NPX;
    const int r   = gid % NPX;
    const int oh  = r / PPR;
    const int ow0 = (r % PPR) * 2;

    unsigned long long acc[2][NPAIR];
#pragma unroll
    for (int p = 0; p < NPAIR; p++) {
        unsigned long long b = pack2(bsm[2 * p], bsm[2 * p + 1]);
        acc[0][p] = b; acc[1][p] = b;
    }

    const float* img = in + (long)n * CIN * IH * IW;
    const int ih0 = oh * STR - PAD;
    const int iw0 = ow0 * STR - PAD;

    for (int ci = 0; ci < CIN; ci++) {
        const float* cp = img + ci * IH * IW;
        float sc = INBN ? scsm[ci] : 0.f;
        float sh = INBN ? shsm[ci] : 0.f;
        float pd[KH][PW];
#pragma unroll
        for (int rr = 0; rr < KH; rr++) {
            int ih = ih0 + rr;
#pragma unroll
            for (int cc = 0; cc < PW; cc++) {
                int iw = iw0 + cc;
                float v = 0.f;
                if (PAD == 0 || ((unsigned)ih < (unsigned)IH && (unsigned)iw < (unsigned)IW))
                    v = __ldg(cp + ih * IW + iw);
                if (INBN) v = fmaxf(fmaf(v, sc, sh), 0.f);
                pd[rr][cc] = v;
            }
        }
        const float* wc = wsm + ci * TAPS * COUTB;
#pragma unroll
        for (int rr = 0; rr < KH; rr++) {
#pragma unroll
            for (int q = 0; q < KW; q++) {
                const ulonglong2* wp = (const ulonglong2*)(wc + (rr * KW + q) * COUTB);
                unsigned long long p0 = pack_dup(pd[rr][q]);
                unsigned long long p1 = pack_dup(pd[rr][q + STR]);
#pragma unroll
                for (int p2 = 0; p2 < NPAIR / 2; p2++) {
                    ulonglong2 w = wp[p2];
                    acc[0][2 * p2]     = ffma2(p0, w.x, acc[0][2 * p2]);
                    acc[1][2 * p2]     = ffma2(p1, w.x, acc[1][2 * p2]);
                    acc[0][2 * p2 + 1] = ffma2(p0, w.y, acc[0][2 * p2 + 1]);
                    acc[1][2 * p2 + 1] = ffma2(p1, w.y, acc[1][2 * p2 + 1]);
                }
            }
        }
    }

    float* op = out + (((long)n * COUT + cg * COUTB) * OH + oh) * OW + ow0;
#pragma unroll
    for (int p = 0; p < NPAIR; p++) {
        float2 a0 = unpack2(acc[0][p]);
        float2 a1 = unpack2(acc[1][p]);
        *(float2*)(op + (2 * p)     * OH * OW) = make_float2(a0.x, a1.x);
        *(float2*)(op + (2 * p + 1) * OH * OW) = make_float2(a0.y, a1.y);
    }
}

// ---------------- weight pre-transpose + bf16 split: [co][ci][tap] -> [tap][co][ci]
template <int CIN, int COUT>
__global__ void prep_w(const float* __restrict__ w,
                       __nv_bfloat16* __restrict__ wh, __nv_bfloat16* __restrict__ wl)
{
    int i = blockIdx.x * 256 + threadIdx.x;
    if (i >= 9 * COUT * CIN) return;
    int ci = i % CIN;
    int co = (i / CIN) % COUT;
    int t  = i / (CIN * COUT);
    float v = __ldg(w + ((size_t)co * CIN + ci) * 9 + t);
    __nv_bfloat16 h = __float2bfloat16(v);
    wh[i] = h;
    wl[i] = __float2bfloat16(v - __bfloat162float(h));
}

// ---------------- HMMA implicit-GEMM conv (3x3, stride 1, pad 0) ----------------
template <int CIN, int COUT, int IW_, int IH_, int OW_, int OH_, int RT>
__global__ void __launch_bounds__(256, 1) conv_hmma(
    const float* __restrict__ in,
    const __nv_bfloat16* __restrict__ wth, const __nv_bfloat16* __restrict__ wtl,
    const float* __restrict__ bias,
    const float* __restrict__ isc, const float* __restrict__ ish,
    float* __restrict__ out)
{
    constexpr int MT     = 192;
    constexpr int PADCI  = CIN + 8;
    constexpr int WN     = COUT / 2;
    constexpr int NP     = WN / 16;
    constexpr int KS     = CIN / 16;
    constexpr int NPX_T  = RT * IW_;
    constexpr int INP_B  = NPX_T * PADCI * 2;
    constexpr int WTAP_B = COUT * PADCI * 2;
    constexpr int CH     = COUT * (CIN / 8);

    extern __shared__ __align__(16) char sm[];
    __nv_bfloat16* inp_h = (__nv_bfloat16*)(sm);
    __nv_bfloat16* inp_l = (__nv_bfloat16*)(sm + INP_B);
    char*  wb     = sm + 2 * INP_B;
    float* bias_s = (float*)(sm + 2 * INP_B + 4 * WTAP_B);
    float* sc_s   = bias_s + COUT;
    float* sh_s   = sc_s + CIN;

    const int tid  = threadIdx.x;
    const int wid  = tid >> 5, lane = tid & 31;
    const int wm   = wid & 3,  wn   = wid >> 2;
    const int nimg = blockIdx.y;
    const int m0   = blockIdx.x * MT;
    const int r_lo = m0 / OW_;

    for (int i = tid; i < COUT; i += 256) bias_s[i] = bias[i];
    for (int i = tid; i < CIN;  i += 256) { sc_s[i] = isc[i]; sh_s[i] = ish[i]; }
    __syncthreads();

    const float* imgp = in + (size_t)nimg * CIN * IH_ * IW_;
    for (int i = tid; i < NPX_T * CIN; i += 256) {
        int px = i % NPX_T, ci = i / NPX_T;
        int row = r_lo + px / IW_; if (row > IH_ - 1) row = IH_ - 1;
        int col = px % IW_;
        float v = __ldg(imgp + ci * IH_ * IW_ + row * IW_ + col);
        v = fmaxf(fmaf(v, sc_s[ci], sh_s[ci]), 0.f);
        __nv_bfloat16 h = __float2bfloat16(v);
        inp_h[px * PADCI + ci] = h;
        inp_l[px * PADCI + ci] = __float2bfloat16(v - __bfloat162float(h));
    }

    auto issue_tap = [&](int t, int buf) {
        uint32_t d_h = smem_u32(wb + (buf * 2 + 0) * WTAP_B);
        uint32_t d_l = smem_u32(wb + (buf * 2 + 1) * WTAP_B);
        const __nv_bfloat16* s_h = wth + (size_t)t * COUT * CIN;
        const __nv_bfloat16* s_l = wtl + (size_t)t * COUT * CIN;
        for (int j = tid; j < CH; j += 256) {
            int co = j / (CIN / 8), seg = j % (CIN / 8);
            uint32_t doff = (uint32_t)(co * PADCI + seg * 8) * 2;
            size_t   soff = (size_t)co * CIN + seg * 8;
            asm volatile("cp.async.cg.shared.global [%0], [%1], 16;"
                         :: "r"(d_h + doff), "l"(s_h + soff) : "memory");
            asm volatile("cp.async.cg.shared.global [%0], [%1], 16;"
                         :: "r"(d_l + doff), "l"(s_l + soff) : "memory");
        }
        asm volatile("cp.async.commit_group;" ::: "memory");
    };
    issue_tap(0, 0);

    int tr0[3], cc0[3];
#pragma unroll
    for (int mi = 0; mi < 3; mi++) {
        int mg = m0 + wm * 48 + mi * 16 + (lane & 15);
        int rr = mg / OW_;
        tr0[mi] = rr - r_lo;
        cc0[mi] = mg - rr * OW_;
    }
    const int acol8 = ((lane >> 4) & 1) * 8;
    const int brow  = ((lane >> 4) & 1) * 8 + (lane & 7);
    const int bcol8 = ((lane >> 3) & 1) * 8;

    float acc[3][2 * NP][4];
#pragma unroll
    for (int a = 0; a < 3; a++)
#pragma unroll
        for (int b = 0; b < 2 * NP; b++)
#pragma unroll
            for (int q = 0; q < 4; q++) acc[a][b][q] = 0.f;

    const uint32_t ih_b = smem_u32(inp_h), il_b = smem_u32(inp_l);

    for (int t = 0; t < 9; t++) {
        __syncthreads();
        if (t < 8) {
            issue_tap(t + 1, (t + 1) & 1);
            asm volatile("cp.async.wait_group 1;" ::: "memory");
        } else {
            asm volatile("cp.async.wait_group 0;" ::: "memory");
        }
        __syncthreads();

        const int dr = t / 3, dc = t - dr * 3;
        const uint32_t wh_b = smem_u32(wb + ((t & 1) * 2 + 0) * WTAP_B);
        const uint32_t wl_b = smem_u32(wb + ((t & 1) * 2 + 1) * WTAP_B);

#pragma unroll
        for (int ks = 0; ks < KS; ks++) {
            const int k0 = ks * 16;
            uint32_t ah[3][4], al[3][4], bh[NP][4], bl[NP][4];
#pragma unroll
            for (int mi = 0; mi < 3; mi++) {
                int tr = tr0[mi] + dr; if (tr > RT - 1) tr = RT - 1;
                uint32_t off = (uint32_t)((tr * IW_ + cc0[mi] + dc) * PADCI + k0 + acol8) * 2;
                ldsm4(ah[mi], ih_b + off);
                ldsm4(al[mi], il_b + off);
            }
#pragma unroll
            for (int p = 0; p < NP; p++) {
                uint32_t off = (uint32_t)((wn * WN + p * 16 + brow) * PADCI + k0 + bcol8) * 2;
                ldsm4(bh[p], wh_b + off);
                ldsm4(bl[p], wl_b + off);
            }
#pragma unroll
            for (int mi = 0; mi < 3; mi++)
#pragma unroll
                for (int p = 0; p < NP; p++) {
                    mma16816(acc[mi][2 * p],     ah[mi], bh[p][0], bh[p][1]);
                    mma16816(acc[mi][2 * p + 1], ah[mi], bh[p][2], bh[p][3]);
                    mma16816(acc[mi][2 * p],     ah[mi], bl[p][0], bl[p][1]);
                    mma16816(acc[mi][2 * p + 1], ah[mi], bl[p][2], bl[p][3]);
                    mma16816(acc[mi][2 * p],     al[mi], bh[p][0], bh[p][1]);
                    mma16816(acc[mi][2 * p + 1], al[mi], bh[p][2], bh[p][3]);
                }
        }
    }

    const size_t obase = (size_t)nimg * COUT * OH_ * OW_;
#pragma unroll
    for (int mi = 0; mi < 3; mi++) {
        int pxa = m0 + wm * 48 + mi * 16 + (lane >> 2);
#pragma unroll
        for (int nj = 0; nj < 2 * NP; nj++) {
            int co = wn * WN + nj * 8 + (lane & 3) * 2;
            float b0 = bias_s[co], b1 = bias_s[co + 1];
            if (pxa < OH_ * OW_) {
                out[obase + (size_t)co * OH_ * OW_ + pxa]       = acc[mi][nj][0] + b0;
                out[obase + (size_t)(co + 1) * OH_ * OW_ + pxa] = acc[mi][nj][1] + b1;
            }
            int pxb = pxa + 8;
            if (pxb < OH_ * OW_) {
                out[obase + (size_t)co * OH_ * OW_ + pxb]       = acc[mi][nj][2] + b0;
                out[obase + (size_t)(co + 1) * OH_ * OW_ + pxb] = acc[mi][nj][3] + b1;
            }
        }
    }
}

// ---------------- BN statistics: coalesced float4 streaming, no divisions -------
__global__ void __launch_bounds__(256) stats_partial(const float* __restrict__ y,
                                                     int C, int plane,
                                                     float* __restrict__ part)
{
    const int c     = blockIdx.x;
    const int tid   = threadIdx.x;
    const int n0    = blockIdx.y * 8;
    const int pv    = plane >> 2;
    __shared__ float ss[256], s2[256];

    float a = 0.f, b = 0.f;
#pragma unroll 1
    for (int n = n0; n < n0 + 8; n++) {
        const float4* p = (const float4*)(y + ((long)n * C + c) * plane);
        for (int i = tid; i < pv; i += 256) {
            float4 v = __ldg(p + i);
            a += v.x + v.y + v.z + v.w;
            b += v.x * v.x + v.y * v.y + v.z * v.z + v.w * v.w;
        }
    }
    ss[tid] = a; s2[tid] = b;
    __syncthreads();
    for (int s = 128; s > 0; s >>= 1) {
        if (tid < s) { ss[tid] += ss[tid + s]; s2[tid] += s2[tid + s]; }
        __syncthreads();
    }
    if (tid == 0) {
        part[(c * 64 + blockIdx.y) * 2 + 0] = ss[0];
        part[(c * 64 + blockIdx.y) * 2 + 1] = s2[0];
    }
}

__global__ void stats_final(const float* __restrict__ part, float invM,
                            const float* __restrict__ g, const float* __restrict__ be,
                            float* __restrict__ sc, float* __restrict__ sh)
{
    const int c = blockIdx.x, t = threadIdx.x;
    __shared__ float ss[64], s2[64];
    ss[t] = part[(c * 64 + t) * 2 + 0];
    s2[t] = part[(c * 64 + t) * 2 + 1];
    __syncthreads();
    for (int s = 32; s > 0; s >>= 1) {
        if (t < s) { ss[t] += ss[t + s]; s2[t] += s2[t + s]; }
        __syncthreads();
    }
    if (t == 0) {
        float mu    = ss[0] * invM;
        float var   = fmaxf(s2[0] * invM - mu * mu, 0.f);
        float scale = g[c] * rsqrtf(var + 1e-5f);
        sc[c] = scale;
        sh[c] = be[c] - mu * scale;
    }
}

// ---------------- GAP (fused BN+ReLU) + L2 normalize + bf16 split ----------------
__global__ void gap_norm(const float* __restrict__ y4, const float* __restrict__ sc,
                         const float* __restrict__ sh, float* __restrict__ f32,
                         __nv_bfloat16* __restrict__ fhi, __nv_bfloat16* __restrict__ flo)
{
    const int n = blockIdx.x, c = threadIdx.x;   // 128 threads
    const float4* p = (const float4*)(y4 + ((long)n * 128 + c) * 576);
    const float scale = sc[c], shift = sh[c];
    float s = 0.f;
#pragma unroll 4
    for (int i = 0; i < 144; i++) {
        float4 v = __ldg(p + i);
        s += fmaxf(fmaf(v.x, scale, shift), 0.f) + fmaxf(fmaf(v.y, scale, shift), 0.f)
           + fmaxf(fmaf(v.z, scale, shift), 0.f) + fmaxf(fmaf(v.w, scale, shift), 0.f);
    }
    float f = s * (1.f / 576.f);
    __shared__ float sq[128];
    sq[c] = f * f;
    __syncthreads();
    for (int st = 64; st > 0; st >>= 1) {
        if (c < st) sq[c] += sq[c + st];
        __syncthreads();
    }
    float inv = 1.f / fmaxf(sqrtf(sq[0]), 1e-12f);
    float v = f * inv;
    f32[n * 128 + c] = v;
    __nv_bfloat16 h = __float2bfloat16(v);
    fhi[n * 128 + c] = h;
    flo[n * 128 + c] = __float2bfloat16(v - __bfloat162float(h));
}

// ---------------- ArcFace weight row normalization + bf16 split ----------------
__global__ void wnorm_split(const float* __restrict__ w,
                            __nv_bfloat16* __restrict__ whi, __nv_bfloat16* __restrict__ wlo)
{
    const int row  = blockIdx.x * 8 + (threadIdx.x >> 5);
    const int lane = threadIdx.x & 31;
    if (row >= NCLS) return;
    float4 v = __ldg((const float4*)(w + (long)row * 128) + lane);
    float s = v.x * v.x + v.y * v.y + v.z * v.z + v.w * v.w;
#pragma unroll
    for (int o = 16; o > 0; o >>= 1) s += __shfl_xor_sync(0xffffffffu, s, o);
    float inv = 1.f / fmaxf(sqrtf(s), 1e-12f);
    float n0 = v.x * inv, n1 = v.y * inv, n2 = v.z * inv, n3 = v.w * inv;
    __nv_bfloat16 h0 = __float2bfloat16(n0), h1 = __float2bfloat16(n1);
    __nv_bfloat16 h2 = __float2bfloat16(n2), h3 = __float2bfloat16(n3);
    __nv_bfloat162 hp0; hp0.x = h0; hp0.y = h1;
    __nv_bfloat162 hp1; hp1.x = h2; hp1.y = h3;
    __nv_bfloat162 lp0;
    lp0.x = __float2bfloat16(n0 - __bfloat162float(h0));
    lp0.y = __float2bfloat16(n1 - __bfloat162float(h1));
    __nv_bfloat162 lp1;
    lp1.x = __float2bfloat16(n2 - __bfloat162float(h2));
    lp1.y = __float2bfloat16(n3 - __bfloat162float(h3));
    *(__nv_bfloat162*)(whi + (long)row * 128 + lane * 4)     = hp0;
    *(__nv_bfloat162*)(whi + (long)row * 128 + lane * 4 + 2) = hp1;
    *(__nv_bfloat162*)(wlo + (long)row * 128 + lane * 4)     = lp0;
    *(__nv_bfloat162*)(wlo + (long)row * 128 + lane * 4 + 2) = lp1;
}

// ---------------- split-bf16 cosine GEMM via mma.sync (HMMA) ----------------
// grid (n_tiles, 4): co-resident CTAs cover one contiguous output n-window
// (B fits in L2 regardless; this ordering keeps output stores local).
#define GSTR 136
#define GT_BYTES (128 * GSTR * 2)

__global__ void __launch_bounds__(256) arc_gemm(
    const __nv_bfloat16* __restrict__ fhi, const __nv_bfloat16* __restrict__ flo,
    const __nv_bfloat16* __restrict__ whi, const __nv_bfloat16* __restrict__ wlo,
    float* __restrict__ out)
{
    extern __shared__ __align__(16) char sm[];
    __nv_bfloat16* Ah = (__nv_bfloat16*)(sm);
    __nv_bfloat16* Al = (__nv_bfloat16*)(sm + GT_BYTES);
    __nv_bfloat16* Bh = (__nv_bfloat16*)(sm + 2 * GT_BYTES);
    __nv_bfloat16* Bl = (__nv_bfloat16*)(sm + 3 * GT_BYTES);

    const int tid  = threadIdx.x;
    const int wid  = tid >> 5, lane = tid & 31;
    const int m0   = blockIdx.y * 128;
    const int n0   = blockIdx.x * 128;
    const int wm0  = (wid & 3) * 32;
    const int wn0  = (wid >> 2) * 64;

    for (int i = tid; i < 128 * 16; i += 256) {
        int row = i >> 4, seg = (i & 15) << 3;
        uint4 vh = *(const uint4*)(fhi + (long)(m0 + row) * 128 + seg);
        uint4 vl = *(const uint4*)(flo + (long)(m0 + row) * 128 + seg);
        *(uint4*)(Ah + row * GSTR + seg) = vh;
        *(uint4*)(Al + row * GSTR + seg) = vl;
        int cls = n0 + row;
        uint4 wh = make_uint4(0, 0, 0, 0), wl = make_uint4(0, 0, 0, 0);
        if (cls < NCLS) {
            wh = *(const uint4*)(whi + (long)cls * 128 + seg);
            wl = *(const uint4*)(wlo + (long)cls * 128 + seg);
        }
        *(uint4*)(Bh + row * GSTR + seg) = wh;
        *(uint4*)(Bl + row * GSTR + seg) = wl;
    }
    __syncthreads();

    float acc[2][8][4];
#pragma unroll
    for (int i = 0; i < 2; i++)
#pragma unroll
        for (int j = 0; j < 8; j++)
#pragma unroll
            for (int q = 0; q < 4; q++) acc[i][j][q] = 0.f;

    const int arow = lane & 15, acol8 = (lane >> 4) & 1;
    const int brow = ((lane >> 4) & 1) * 8 + (lane & 7);
    const int bcol8 = (lane >> 3) & 1;

#pragma unroll
    for (int ks = 0; ks < 8; ks++) {
        const int k0 = ks * 16;
        uint32_t ah[2][4], al[2][4], bh[4][4], bl[4][4];
#pragma unroll
        for (int mi = 0; mi < 2; mi++) {
            uint32_t off = ((wm0 + mi * 16 + arow) * GSTR + k0 + acol8 * 8) * 2;
            ldsm4(ah[mi], smem_u32(Ah) + off);
            ldsm4(al[mi], smem_u32(Al) + off);
        }
#pragma unroll
        for (int p = 0; p < 4; p++) {
            uint32_t off = ((wn0 + p * 16 + brow) * GSTR + k0 + bcol8 * 8) * 2;
            ldsm4(bh[p], smem_u32(Bh) + off);
            ldsm4(bl[p], smem_u32(Bl) + off);
        }
#pragma unroll
        for (int mi = 0; mi < 2; mi++) {
#pragma unroll
            for (int p = 0; p < 4; p++) {
                mma16816(acc[mi][2 * p],     ah[mi], bh[p][0], bh[p][1]);
                mma16816(acc[mi][2 * p + 1], ah[mi], bh[p][2], bh[p][3]);
                mma16816(acc[mi][2 * p],     ah[mi], bl[p][0], bl[p][1]);
                mma16816(acc[mi][2 * p + 1], ah[mi], bl[p][2], bl[p][3]);
                mma16816(acc[mi][2 * p],     al[mi], bh[p][0], bh[p][1]);
                mma16816(acc[mi][2 * p + 1], al[mi], bh[p][2], bh[p][3]);
            }
        }
    }

#pragma unroll
    for (int mi = 0; mi < 2; mi++) {
#pragma unroll
        for (int nj = 0; nj < 8; nj++) {
            int m = m0 + wm0 + mi * 16 + (lane >> 2);
            int n = n0 + wn0 + nj * 8 + (lane & 3) * 2;
            if (n < NCLS) {
                float* c = acc[mi][nj];
                *(float2*)(out + (long)m * NCLS + n) =
                    make_float2(64.f * c[0], 64.f * c[1]);
                *(float2*)(out + (long)(m + 8) * NCLS + n) =
                    make_float2(64.f * c[2], 64.f * c[3]);
            }
        }
    }
}

// ---------------- ArcFace margin: exact fp32 target logit + margin ----------------
__global__ void margin_kernel(float* __restrict__ out, const int* __restrict__ gt,
                              const float* __restrict__ f32, const float* __restrict__ arc)
{
    const int r    = blockIdx.x * 4 + (threadIdx.x >> 5);
    const int lane = threadIdx.x & 31;
    if (r >= N_IMG) return;
    const int c = gt[r];
    float4 wv = __ldg((const float4*)(arc + (long)c * 128) + lane);
    float4 fv = *((const float4*)(f32 + (long)r * 128) + lane);
    float ws = wv.x * wv.x + wv.y * wv.y + wv.z * wv.z + wv.w * wv.w;
    float dt = wv.x * fv.x + wv.y * fv.y + wv.z * fv.z + wv.w * fv.w;
#pragma unroll
    for (int o = 16; o > 0; o >>= 1) {
        ws += __shfl_xor_sync(0xffffffffu, ws, o);
        dt += __shfl_xor_sync(0xffffffffu, dt, o);
    }
    if (lane == 0) {
        float t = dt / fmaxf(sqrtf(ws), 1e-12f);
        t = fminf(fmaxf(t, -1.f), 1.f);
        out[(long)r * NCLS + c] = 64.f * cosf(acosf(t) + 0.5f);
    }
}

// ---------------- launcher ----------------
extern "C" void kernel_launch(void* const* d_in, const int* in_sizes, int n_in,
                              void* d_out, int out_size)
{
    (void)in_sizes; (void)n_in; (void)out_size;
    const float* x   = (const float*)d_in[0];
    const int*   gt  = (const int*)d_in[1];
    const float* w1  = (const float*)d_in[2];
    const float* b1  = (const float*)d_in[3];
    const float* g1  = (const float*)d_in[4];
    const float* be1 = (const float*)d_in[5];
    const float* w2  = (const float*)d_in[6];
    const float* b2  = (const float*)d_in[7];
    const float* g2  = (const float*)d_in[8];
    const float* be2 = (const float*)d_in[9];
    const float* w3  = (const float*)d_in[10];
    const float* b3  = (const float*)d_in[11];
    const float* g3  = (const float*)d_in[12];
    const float* be3 = (const float*)d_in[13];
    const float* w4  = (const float*)d_in[14];
    const float* b4  = (const float*)d_in[15];
    const float* g4  = (const float*)d_in[16];
    const float* be4 = (const float*)d_in[17];
    const float* arc = (const float*)d_in[18];
    float* outp = (float*)d_out;

    float *y1, *y2, *y3, *y4, *f32, *part, *bns, *bnsh;
    __nv_bfloat16 *fhi, *flo, *whi, *wlo, *wt3h, *wt3l, *wt4h, *wt4l;
    cudaGetSymbolAddress((void**)&y1,   g_y1);
    cudaGetSymbolAddress((void**)&y2,   g_y2);
    cudaGetSymbolAddress((void**)&y3,   g_y3);
    cudaGetSymbolAddress((void**)&y4,   g_y4);
    cudaGetSymbolAddress((void**)&f32,  g_f32);
    cudaGetSymbolAddress((void**)&fhi,  g_fhi);
    cudaGetSymbolAddress((void**)&flo,  g_flo);
    cudaGetSymbolAddress((void**)&whi,  g_whi);
    cudaGetSymbolAddress((void**)&wlo,  g_wlo);
    cudaGetSymbolAddress((void**)&wt3h, g_wt3h);
    cudaGetSymbolAddress((void**)&wt3l, g_wt3l);
    cudaGetSymbolAddress((void**)&wt4h, g_wt4h);
    cudaGetSymbolAddress((void**)&wt4l, g_wt4l);
    cudaGetSymbolAddress((void**)&part, g_part);
    cudaGetSymbolAddress((void**)&bns,  g_bns);
    cudaGetSymbolAddress((void**)&bnsh, g_bnsh);

    // weight pre-transpose for HMMA convs
    prep_w<32, 64><<<(9 * 64 * 32 + 255) / 256, 256>>>(w3, wt3h, wt3l);
    prep_w<64, 128><<<(9 * 128 * 64 + 255) / 256, 256>>>(w4, wt4h, wt4l);

    // layer 1: conv(1->16, 4x4, s2, p1) 112 -> 56  (direct FFMA2)
    conv_fwd<1, 16, 16, 4, 4, 2, 1, 112, 112, 56, 56, false>
        <<<3136, 256>>>(x, w1, b1, nullptr, nullptr, y1);
    stats_partial<<<dim3(16, 64), 256>>>(y1, 16, 3136, part);
    stats_final<<<16, 64>>>(part, 1.f / (512.f * 3136.f), g1, be1, bns + 0, bnsh + 0);

    // layer 2: conv(16->32, 4x4, s2, p1) 56 -> 28  (direct FFMA2)
    conv_fwd<16, 32, 32, 4, 4, 2, 1, 56, 56, 28, 28, true>
        <<<dim3(784, 1), 256>>>(y1, w2, b2, bns + 0, bnsh + 0, y2);
    stats_partial<<<dim3(32, 64), 256>>>(y2, 32, 784, part);
    stats_final<<<32, 64>>>(part, 1.f / (512.f * 784.f), g2, be2, bns + 128, bnsh + 128);

    // layer 3: conv(32->64, 3x3, s1, p0) 28 -> 26  (HMMA implicit GEMM)
    {
        constexpr int INP_B = 12 * 28 * 40 * 2;
        constexpr int WTAP_B = 64 * 40 * 2;
        constexpr int S3 = 2 * INP_B + 4 * WTAP_B + (64 + 2 * 32) * 4;
        cudaFuncSetAttribute(conv_hmma<32, 64, 28, 28, 26, 26, 12>,
                             cudaFuncAttributeMaxDynamicSharedMemorySize, S3);
        conv_hmma<32, 64, 28, 28, 26, 26, 12>
            <<<dim3(4, 512), 256, S3>>>(y2, wt3h, wt3l, b3, bns + 128, bnsh + 128, y3);
    }
    stats_partial<<<dim3(64, 64), 256>>>(y3, 64, 676, part);
    stats_final<<<64, 64>>>(part, 1.f / (512.f * 676.f), g3, be3, bns + 256, bnsh + 256);

    // layer 4: conv(64->128, 3x3, s1, p0) 26 -> 24  (HMMA implicit GEMM)
    {
        constexpr int INP_B = 10 * 26 * 72 * 2;
        constexpr int WTAP_B = 128 * 72 * 2;
        constexpr int S4 = 2 * INP_B + 4 * WTAP_B + (128 + 2 * 64) * 4;
        cudaFuncSetAttribute(conv_hmma<64, 128, 26, 26, 24, 24, 10>,
                             cudaFuncAttributeMaxDynamicSharedMemorySize, S4);
        conv_hmma<64, 128, 26, 26, 24, 24, 10>
            <<<dim3(3, 512), 256, S4>>>(y3, wt4h, wt4l, b4, bns + 256, bnsh + 256, y4);
    }
    stats_partial<<<dim3(128, 64), 256>>>(y4, 128, 576, part);
    stats_final<<<128, 64>>>(part, 1.f / (512.f * 576.f), g4, be4, bns + 384, bnsh + 384);

    // GAP (+BN+ReLU fused) + feature normalize (+fp32 copy) + bf16 split
    gap_norm<<<512, 128>>>(y4, bns + 384, bnsh + 384, f32, fhi, flo);

    // arc weight row normalize + bf16 split
    wnorm_split<<<12500, 256>>>(arc, whi, wlo);

    // split-bf16 HMMA cosine GEMM (scaled by 64); grid: n fastest (R6 layout)
    cudaFuncSetAttribute(arc_gemm, cudaFuncAttributeMaxDynamicSharedMemorySize, 4 * GT_BYTES);
    arc_gemm<<<dim3((NCLS + 127) / 128, 4), 256, 4 * GT_BYTES>>>(fhi, flo, whi, wlo, outp);

    // exact margin scatter (fp32 recompute; overwrites target entries)
    margin_kernel<<<128, 128>>>(outp, gt, f32, arc);
}

// round 10
// speedup vs baseline: 1.4564x; 1.4564x over previous
#include <cuda_runtime.h>
#include <cuda_bf16.h>
#include <stdint.h>
#include <math.h>

#define N_IMG 512
#define NCLS  100000

// ---------------- scratch (static device globals; no allocation) ----------------
__device__ float g_y1[512 * 16 * 56 * 56];
__device__ float g_y2[512 * 32 * 28 * 28];
__device__ float g_y3[512 * 64 * 26 * 26];
__device__ float g_y4[512 * 128 * 24 * 24];
__device__ float g_f32[512 * 128];
__device__ __nv_bfloat16 g_fhi[512 * 128];
__device__ __nv_bfloat16 g_flo[512 * 128];
__device__ __nv_bfloat16 g_whi[100000 * 128];
__device__ __nv_bfloat16 g_wlo[100000 * 128];
__device__ __nv_bfloat16 g_wt3h[9 * 64 * 32];
__device__ __nv_bfloat16 g_wt3l[9 * 64 * 32];
__device__ __nv_bfloat16 g_wt4h[9 * 128 * 64];
__device__ __nv_bfloat16 g_wt4l[9 * 128 * 64];
__device__ float g_part[128 * 64 * 2];
__device__ float g_bns[4 * 128];
__device__ float g_bnsh[4 * 128];

// ---------------- packed f32x2 helpers ----------------
__device__ __forceinline__ unsigned long long pack_dup(float x) {
    unsigned long long r; asm("mov.b64 %0,{%1,%1};" : "=l"(r) : "f"(x)); return r;
}
__device__ __forceinline__ unsigned long long pack2(float x, float y) {
    unsigned long long r; asm("mov.b64 %0,{%1,%2};" : "=l"(r) : "f"(x), "f"(y)); return r;
}
__device__ __forceinline__ unsigned long long ffma2(unsigned long long a, unsigned long long b,
                                                    unsigned long long c) {
    unsigned long long d;
    asm("fma.rn.f32x2 %0,%1,%2,%3;" : "=l"(d) : "l"(a), "l"(b), "l"(c));
    return d;
}
__device__ __forceinline__ float2 unpack2(unsigned long long v) {
    float2 f; asm("mov.b64 {%0,%1},%2;" : "=f"(f.x), "=f"(f.y) : "l"(v)); return f;
}

// ---------------- warp-mma helpers ----------------
__device__ __forceinline__ uint32_t smem_u32(const void* p) {
    uint32_t a;
    asm("{ .reg .u64 t; cvta.to.shared.u64 t, %1; cvt.u32.u64 %0, t; }" : "=r"(a) : "l"(p));
    return a;
}
__device__ __forceinline__ void ldsm4(uint32_t* r, uint32_t a) {
    asm volatile("ldmatrix.sync.aligned.m8n8.x4.shared.b16 {%0,%1,%2,%3}, [%4];"
                 : "=r"(r[0]), "=r"(r[1]), "=r"(r[2]), "=r"(r[3]) : "r"(a));
}
__device__ __forceinline__ void mma16816(float* c, const uint32_t* a, uint32_t b0, uint32_t b1) {
    asm volatile(
        "mma.sync.aligned.m16n8k16.row.col.f32.bf16.bf16.f32 "
        "{%0,%1,%2,%3}, {%4,%5,%6,%7}, {%8,%9}, {%0,%1,%2,%3};"
        : "+f"(c[0]), "+f"(c[1]), "+f"(c[2]), "+f"(c[3])
        : "r"(a[0]), "r"(a[1]), "r"(a[2]), "r"(a[3]), "r"(b0), "r"(b1));
}

// ---------------- direct conv (conv1 / conv2 only) ----------------
template <int CIN, int COUT, int COUTB, int KH, int KW, int STR, int PAD,
          int IH, int IW, int OH, int OW, bool INBN>
__global__ void __launch_bounds__(256, 2) conv_fwd(
    const float* __restrict__ in, const float* __restrict__ wgl,
    const float* __restrict__ bias,
    const float* __restrict__ isc, const float* __restrict__ ish,
    float* __restrict__ out)
{
    constexpr int TAPS  = KH * KW;
    constexpr int NPAIR = COUTB / 2;
    constexpr int PW    = KW + STR;
    constexpr int PPR   = OW / 2;
    constexpr int NPX   = OH * PPR;

    __shared__ __align__(16) float wsm[CIN * TAPS * COUTB];
    __shared__ float bsm[COUTB];
    __shared__ float scsm[CIN], shsm[CIN];

    const int tid = threadIdx.x;
    const int cg  = blockIdx.y;

    for (int i = tid; i < CIN * TAPS * COUTB; i += 256) {
        int co  = i % COUTB;
        int tap = (i / COUTB) % TAPS;
        int ci  = i / (COUTB * TAPS);
        wsm[i] = wgl[((cg * COUTB + co) * CIN + ci) * TAPS + tap];
    }
    if (tid < COUTB) bsm[tid] = bias[cg * COUTB + tid];
    if (INBN) {
        for (int i = tid; i < CIN; i += 256) { scsm[i] = isc[i]; shsm[i] = ish[i]; }
    }
    __syncthreads();

    const int gid = blockIdx.x * 256 + tid;
    if (gid >= N_IMG * NPX) return;
    const int n   = gid / NPX;
    const int r   = gid % NPX;
    const int oh  = r / PPR;
    const int ow0 = (r % PPR) * 2;

    unsigned long long acc[2][NPAIR];
#pragma unroll
    for (int p = 0; p < NPAIR; p++) {
        unsigned long long b = pack2(bsm[2 * p], bsm[2 * p + 1]);
        acc[0][p] = b; acc[1][p] = b;
    }

    const float* img = in + (long)n * CIN * IH * IW;
    const int ih0 = oh * STR - PAD;
    const int iw0 = ow0 * STR - PAD;

    for (int ci = 0; ci < CIN; ci++) {
        const float* cp = img + ci * IH * IW;
        float sc = INBN ? scsm[ci] : 0.f;
        float sh = INBN ? shsm[ci] : 0.f;
        float pd[KH][PW];
#pragma unroll
        for (int rr = 0; rr < KH; rr++) {
            int ih = ih0 + rr;
#pragma unroll
            for (int cc = 0; cc < PW; cc++) {
                int iw = iw0 + cc;
                float v = 0.f;
                if (PAD == 0 || ((unsigned)ih < (unsigned)IH && (unsigned)iw < (unsigned)IW))
                    v = __ldg(cp + ih * IW + iw);
                if (INBN) v = fmaxf(fmaf(v, sc, sh), 0.f);
                pd[rr][cc] = v;
            }
        }
        const float* wc = wsm + ci * TAPS * COUTB;
#pragma unroll
        for (int rr = 0; rr < KH; rr++) {
#pragma unroll
            for (int q = 0; q < KW; q++) {
                const ulonglong2* wp = (const ulonglong2*)(wc + (rr * KW + q) * COUTB);
                unsigned long long p0 = pack_dup(pd[rr][q]);
                unsigned long long p1 = pack_dup(pd[rr][q + STR]);
#pragma unroll
                for (int p2 = 0; p2 < NPAIR / 2; p2++) {
                    ulonglong2 w = wp[p2];
                    acc[0][2 * p2]     = ffma2(p0, w.x, acc[0][2 * p2]);
                    acc[1][2 * p2]     = ffma2(p1, w.x, acc[1][2 * p2]);
                    acc[0][2 * p2 + 1] = ffma2(p0, w.y, acc[0][2 * p2 + 1]);
                    acc[1][2 * p2 + 1] = ffma2(p1, w.y, acc[1][2 * p2 + 1]);
                }
            }
        }
    }

    float* op = out + (((long)n * COUT + cg * COUTB) * OH + oh) * OW + ow0;
#pragma unroll
    for (int p = 0; p < NPAIR; p++) {
        float2 a0 = unpack2(acc[0][p]);
        float2 a1 = unpack2(acc[1][p]);
        *(float2*)(op + (2 * p)     * OH * OW) = make_float2(a0.x, a1.x);
        *(float2*)(op + (2 * p + 1) * OH * OW) = make_float2(a0.y, a1.y);
    }
}

// ---------------- weight pre-transpose + bf16 split: [co][ci][tap] -> [tap][co][ci]
template <int CIN, int COUT>
__global__ void prep_w(const float* __restrict__ w,
                       __nv_bfloat16* __restrict__ wh, __nv_bfloat16* __restrict__ wl)
{
    int i = blockIdx.x * 256 + threadIdx.x;
    if (i >= 9 * COUT * CIN) return;
    int ci = i % CIN;
    int co = (i / CIN) % COUT;
    int t  = i / (CIN * COUT);
    float v = __ldg(w + ((size_t)co * CIN + ci) * 9 + t);
    __nv_bfloat16 h = __float2bfloat16(v);
    wh[i] = h;
    wl[i] = __float2bfloat16(v - __bfloat162float(h));
}

// ---------------- HMMA implicit-GEMM conv (3x3, stride 1, pad 0) ----------------
template <int CIN, int COUT, int IW_, int IH_, int OW_, int OH_, int RT>
__global__ void __launch_bounds__(256, 1) conv_hmma(
    const float* __restrict__ in,
    const __nv_bfloat16* __restrict__ wth, const __nv_bfloat16* __restrict__ wtl,
    const float* __restrict__ bias,
    const float* __restrict__ isc, const float* __restrict__ ish,
    float* __restrict__ out)
{
    constexpr int MT     = 192;
    constexpr int PADCI  = CIN + 8;
    constexpr int WN     = COUT / 2;
    constexpr int NP     = WN / 16;
    constexpr int KS     = CIN / 16;
    constexpr int NPX_T  = RT * IW_;
    constexpr int INP_B  = NPX_T * PADCI * 2;
    constexpr int WTAP_B = COUT * PADCI * 2;
    constexpr int CH     = COUT * (CIN / 8);

    extern __shared__ __align__(16) char sm[];
    __nv_bfloat16* inp_h = (__nv_bfloat16*)(sm);
    __nv_bfloat16* inp_l = (__nv_bfloat16*)(sm + INP_B);
    char*  wb     = sm + 2 * INP_B;
    float* bias_s = (float*)(sm + 2 * INP_B + 4 * WTAP_B);
    float* sc_s   = bias_s + COUT;
    float* sh_s   = sc_s + CIN;

    const int tid  = threadIdx.x;
    const int wid  = tid >> 5, lane = tid & 31;
    const int wm   = wid & 3,  wn   = wid >> 2;
    const int nimg = blockIdx.y;
    const int m0   = blockIdx.x * MT;
    const int r_lo = m0 / OW_;

    for (int i = tid; i < COUT; i += 256) bias_s[i] = bias[i];
    for (int i = tid; i < CIN;  i += 256) { sc_s[i] = isc[i]; sh_s[i] = ish[i]; }
    __syncthreads();

    const float* imgp = in + (size_t)nimg * CIN * IH_ * IW_;
    for (int i = tid; i < NPX_T * CIN; i += 256) {
        int px = i % NPX_T, ci = i / NPX_T;
        int row = r_lo + px / IW_; if (row > IH_ - 1) row = IH_ - 1;
        int col = px % IW_;
        float v = __ldg(imgp + ci * IH_ * IW_ + row * IW_ + col);
        v = fmaxf(fmaf(v, sc_s[ci], sh_s[ci]), 0.f);
        __nv_bfloat16 h = __float2bfloat16(v);
        inp_h[px * PADCI + ci] = h;
        inp_l[px * PADCI + ci] = __float2bfloat16(v - __bfloat162float(h));
    }

    auto issue_tap = [&](int t, int buf) {
        uint32_t d_h = smem_u32(wb + (buf * 2 + 0) * WTAP_B);
        uint32_t d_l = smem_u32(wb + (buf * 2 + 1) * WTAP_B);
        const __nv_bfloat16* s_h = wth + (size_t)t * COUT * CIN;
        const __nv_bfloat16* s_l = wtl + (size_t)t * COUT * CIN;
        for (int j = tid; j < CH; j += 256) {
            int co = j / (CIN / 8), seg = j % (CIN / 8);
            uint32_t doff = (uint32_t)(co * PADCI + seg * 8) * 2;
            size_t   soff = (size_t)co * CIN + seg * 8;
            asm volatile("cp.async.cg.shared.global [%0], [%1], 16;"
                         :: "r"(d_h + doff), "l"(s_h + soff) : "memory");
            asm volatile("cp.async.cg.shared.global [%0], [%1], 16;"
                         :: "r"(d_l + doff), "l"(s_l + soff) : "memory");
        }
        asm volatile("cp.async.commit_group;" ::: "memory");
    };
    issue_tap(0, 0);

    int tr0[3], cc0[3];
#pragma unroll
    for (int mi = 0; mi < 3; mi++) {
        int mg = m0 + wm * 48 + mi * 16 + (lane & 15);
        int rr = mg / OW_;
        tr0[mi] = rr - r_lo;
        cc0[mi] = mg - rr * OW_;
    }
    const int acol8 = ((lane >> 4) & 1) * 8;
    const int brow  = ((lane >> 4) & 1) * 8 + (lane & 7);
    const int bcol8 = ((lane >> 3) & 1) * 8;

    float acc[3][2 * NP][4];
#pragma unroll
    for (int a = 0; a < 3; a++)
#pragma unroll
        for (int b = 0; b < 2 * NP; b++)
#pragma unroll
            for (int q = 0; q < 4; q++) acc[a][b][q] = 0.f;

    const uint32_t ih_b = smem_u32(inp_h), il_b = smem_u32(inp_l);

    for (int t = 0; t < 9; t++) {
        __syncthreads();
        if (t < 8) {
            issue_tap(t + 1, (t + 1) & 1);
            asm volatile("cp.async.wait_group 1;" ::: "memory");
        } else {
            asm volatile("cp.async.wait_group 0;" ::: "memory");
        }
        __syncthreads();

        const int dr = t / 3, dc = t - dr * 3;
        const uint32_t wh_b = smem_u32(wb + ((t & 1) * 2 + 0) * WTAP_B);
        const uint32_t wl_b = smem_u32(wb + ((t & 1) * 2 + 1) * WTAP_B);

#pragma unroll
        for (int ks = 0; ks < KS; ks++) {
            const int k0 = ks * 16;
            uint32_t ah[3][4], al[3][4], bh[NP][4], bl[NP][4];
#pragma unroll
            for (int mi = 0; mi < 3; mi++) {
                int tr = tr0[mi] + dr; if (tr > RT - 1) tr = RT - 1;
                uint32_t off = (uint32_t)((tr * IW_ + cc0[mi] + dc) * PADCI + k0 + acol8) * 2;
                ldsm4(ah[mi], ih_b + off);
                ldsm4(al[mi], il_b + off);
            }
#pragma unroll
            for (int p = 0; p < NP; p++) {
                uint32_t off = (uint32_t)((wn * WN + p * 16 + brow) * PADCI + k0 + bcol8) * 2;
                ldsm4(bh[p], wh_b + off);
                ldsm4(bl[p], wl_b + off);
            }
#pragma unroll
            for (int mi = 0; mi < 3; mi++)
#pragma unroll
                for (int p = 0; p < NP; p++) {
                    mma16816(acc[mi][2 * p],     ah[mi], bh[p][0], bh[p][1]);
                    mma16816(acc[mi][2 * p + 1], ah[mi], bh[p][2], bh[p][3]);
                    mma16816(acc[mi][2 * p],     ah[mi], bl[p][0], bl[p][1]);
                    mma16816(acc[mi][2 * p + 1], ah[mi], bl[p][2], bl[p][3]);
                    mma16816(acc[mi][2 * p],     al[mi], bh[p][0], bh[p][1]);
                    mma16816(acc[mi][2 * p + 1], al[mi], bh[p][2], bh[p][3]);
                }
        }
    }

    const size_t obase = (size_t)nimg * COUT * OH_ * OW_;
#pragma unroll
    for (int mi = 0; mi < 3; mi++) {
        int pxa = m0 + wm * 48 + mi * 16 + (lane >> 2);
#pragma unroll
        for (int nj = 0; nj < 2 * NP; nj++) {
            int co = wn * WN + nj * 8 + (lane & 3) * 2;
            float b0 = bias_s[co], b1 = bias_s[co + 1];
            if (pxa < OH_ * OW_) {
                out[obase + (size_t)co * OH_ * OW_ + pxa]       = acc[mi][nj][0] + b0;
                out[obase + (size_t)(co + 1) * OH_ * OW_ + pxa] = acc[mi][nj][1] + b1;
            }
            int pxb = pxa + 8;
            if (pxb < OH_ * OW_) {
                out[obase + (size_t)co * OH_ * OW_ + pxb]       = acc[mi][nj][2] + b0;
                out[obase + (size_t)(co + 1) * OH_ * OW_ + pxb] = acc[mi][nj][3] + b1;
            }
        }
    }
}

// ---------------- BN statistics: coalesced float4 streaming, no divisions -------
__global__ void __launch_bounds__(256) stats_partial(const float* __restrict__ y,
                                                     int C, int plane,
                                                     float* __restrict__ part)
{
    const int c     = blockIdx.x;
    const int tid   = threadIdx.x;
    const int n0    = blockIdx.y * 8;
    const int pv    = plane >> 2;
    __shared__ float ss[256], s2[256];

    float a = 0.f, b = 0.f;
#pragma unroll 1
    for (int n = n0; n < n0 + 8; n++) {
        const float4* p = (const float4*)(y + ((long)n * C + c) * plane);
        for (int i = tid; i < pv; i += 256) {
            float4 v = __ldg(p + i);
            a += v.x + v.y + v.z + v.w;
            b += v.x * v.x + v.y * v.y + v.z * v.z + v.w * v.w;
        }
    }
    ss[tid] = a; s2[tid] = b;
    __syncthreads();
    for (int s = 128; s > 0; s >>= 1) {
        if (tid < s) { ss[tid] += ss[tid + s]; s2[tid] += s2[tid + s]; }
        __syncthreads();
    }
    if (tid == 0) {
        part[(c * 64 + blockIdx.y) * 2 + 0] = ss[0];
        part[(c * 64 + blockIdx.y) * 2 + 1] = s2[0];
    }
}

__global__ void stats_final(const float* __restrict__ part, float invM,
                            const float* __restrict__ g, const float* __restrict__ be,
                            float* __restrict__ sc, float* __restrict__ sh)
{
    const int c = blockIdx.x, t = threadIdx.x;
    __shared__ float ss[64], s2[64];
    ss[t] = part[(c * 64 + t) * 2 + 0];
    s2[t] = part[(c * 64 + t) * 2 + 1];
    __syncthreads();
    for (int s = 32; s > 0; s >>= 1) {
        if (t < s) { ss[t] += ss[t + s]; s2[t] += s2[t + s]; }
        __syncthreads();
    }
    if (t == 0) {
        float mu    = ss[0] * invM;
        float var   = fmaxf(s2[0] * invM - mu * mu, 0.f);
        float scale = g[c] * rsqrtf(var + 1e-5f);
        sc[c] = scale;
        sh[c] = be[c] - mu * scale;
    }
}

// ---------------- GAP (fused BN+ReLU) + L2 normalize + bf16 split ----------------
__global__ void gap_norm(const float* __restrict__ y4, const float* __restrict__ sc,
                         const float* __restrict__ sh, float* __restrict__ f32,
                         __nv_bfloat16* __restrict__ fhi, __nv_bfloat16* __restrict__ flo)
{
    const int n = blockIdx.x, c = threadIdx.x;   // 128 threads
    const float4* p = (const float4*)(y4 + ((long)n * 128 + c) * 576);
    const float scale = sc[c], shift = sh[c];
    float s = 0.f;
#pragma unroll 4
    for (int i = 0; i < 144; i++) {
        float4 v = __ldg(p + i);
        s += fmaxf(fmaf(v.x, scale, shift), 0.f) + fmaxf(fmaf(v.y, scale, shift), 0.f)
           + fmaxf(fmaf(v.z, scale, shift), 0.f) + fmaxf(fmaf(v.w, scale, shift), 0.f);
    }
    float f = s * (1.f / 576.f);
    __shared__ float sq[128];
    sq[c] = f * f;
    __syncthreads();
    for (int st = 64; st > 0; st >>= 1) {
        if (c < st) sq[c] += sq[c + st];
        __syncthreads();
    }
    float inv = 1.f / fmaxf(sqrtf(sq[0]), 1e-12f);
    float v = f * inv;
    f32[n * 128 + c] = v;
    __nv_bfloat16 h = __float2bfloat16(v);
    fhi[n * 128 + c] = h;
    flo[n * 128 + c] = __float2bfloat16(v - __bfloat162float(h));
}

// ---------------- ArcFace weight row normalization + bf16 split ----------------
__global__ void wnorm_split(const float* __restrict__ w,
                            __nv_bfloat16* __restrict__ whi, __nv_bfloat16* __restrict__ wlo)
{
    const int row  = blockIdx.x * 8 + (threadIdx.x >> 5);
    const int lane = threadIdx.x & 31;
    if (row >= NCLS) return;
    float4 v = __ldg((const float4*)(w + (long)row * 128) + lane);
    float s = v.x * v.x + v.y * v.y + v.z * v.z + v.w * v.w;
#pragma unroll
    for (int o = 16; o > 0; o >>= 1) s += __shfl_xor_sync(0xffffffffu, s, o);
    float inv = 1.f / fmaxf(sqrtf(s), 1e-12f);
    float n0 = v.x * inv, n1 = v.y * inv, n2 = v.z * inv, n3 = v.w * inv;
    __nv_bfloat16 h0 = __float2bfloat16(n0), h1 = __float2bfloat16(n1);
    __nv_bfloat16 h2 = __float2bfloat16(n2), h3 = __float2bfloat16(n3);
    __nv_bfloat162 hp0; hp0.x = h0; hp0.y = h1;
    __nv_bfloat162 hp1; hp1.x = h2; hp1.y = h3;
    __nv_bfloat162 lp0;
    lp0.x = __float2bfloat16(n0 - __bfloat162float(h0));
    lp0.y = __float2bfloat16(n1 - __bfloat162float(h1));
    __nv_bfloat162 lp1;
    lp1.x = __float2bfloat16(n2 - __bfloat162float(h2));
    lp1.y = __float2bfloat16(n3 - __bfloat162float(h3));
    *(__nv_bfloat162*)(whi + (long)row * 128 + lane * 4)     = hp0;
    *(__nv_bfloat162*)(whi + (long)row * 128 + lane * 4 + 2) = hp1;
    *(__nv_bfloat162*)(wlo + (long)row * 128 + lane * 4)     = lp0;
    *(__nv_bfloat162*)(wlo + (long)row * 128 + lane * 4 + 2) = lp1;
}

// ---------------- split-bf16 cosine GEMM via mma.sync (HMMA) ----------------
// grid (4, n_tiles): m-tile fastest -> the 4 CTAs sharing one B tile are
// co-resident (B reused via L2 before the output store stream evicts it).
#define GSTR 136
#define GT_BYTES (128 * GSTR * 2)

__global__ void __launch_bounds__(256) arc_gemm(
    const __nv_bfloat16* __restrict__ fhi, const __nv_bfloat16* __restrict__ flo,
    const __nv_bfloat16* __restrict__ whi, const __nv_bfloat16* __restrict__ wlo,
    float* __restrict__ out)
{
    extern __shared__ __align__(16) char sm[];
    __nv_bfloat16* Ah = (__nv_bfloat16*)(sm);
    __nv_bfloat16* Al = (__nv_bfloat16*)(sm + GT_BYTES);
    __nv_bfloat16* Bh = (__nv_bfloat16*)(sm + 2 * GT_BYTES);
    __nv_bfloat16* Bl = (__nv_bfloat16*)(sm + 3 * GT_BYTES);

    const int tid  = threadIdx.x;
    const int wid  = tid >> 5, lane = tid & 31;
    const int m0   = blockIdx.x * 128;
    const int n0   = blockIdx.y * 128;
    const int wm0  = (wid & 3) * 32;
    const int wn0  = (wid >> 2) * 64;

    for (int i = tid; i < 128 * 16; i += 256) {
        int row = i >> 4, seg = (i & 15) << 3;
        uint4 vh = *(const uint4*)(fhi + (long)(m0 + row) * 128 + seg);
        uint4 vl = *(const uint4*)(flo + (long)(m0 + row) * 128 + seg);
        *(uint4*)(Ah + row * GSTR + seg) = vh;
        *(uint4*)(Al + row * GSTR + seg) = vl;
        int cls = n0 + row;
        uint4 wh = make_uint4(0, 0, 0, 0), wl = make_uint4(0, 0, 0, 0);
        if (cls < NCLS) {
            wh = *(const uint4*)(whi + (long)cls * 128 + seg);
            wl = *(const uint4*)(wlo + (long)cls * 128 + seg);
        }
        *(uint4*)(Bh + row * GSTR + seg) = wh;
        *(uint4*)(Bl + row * GSTR + seg) = wl;
    }
    __syncthreads();

    float acc[2][8][4];
#pragma unroll
    for (int i = 0; i < 2; i++)
#pragma unroll
        for (int j = 0; j < 8; j++)
#pragma unroll
            for (int q = 0; q < 4; q++) acc[i][j][q] = 0.f;

    const int arow = lane & 15, acol8 = (lane >> 4) & 1;
    const int brow = ((lane >> 4) & 1) * 8 + (lane & 7);
    const int bcol8 = (lane >> 3) & 1;

#pragma unroll
    for (int ks = 0; ks < 8; ks++) {
        const int k0 = ks * 16;
        uint32_t ah[2][4], al[2][4], bh[4][4], bl[4][4];
#pragma unroll
        for (int mi = 0; mi < 2; mi++) {
            uint32_t off = ((wm0 + mi * 16 + arow) * GSTR + k0 + acol8 * 8) * 2;
            ldsm4(ah[mi], smem_u32(Ah) + off);
            ldsm4(al[mi], smem_u32(Al) + off);
        }
#pragma unroll
        for (int p = 0; p < 4; p++) {
            uint32_t off = ((wn0 + p * 16 + brow) * GSTR + k0 + bcol8 * 8) * 2;
            ldsm4(bh[p], smem_u32(Bh) + off);
            ldsm4(bl[p], smem_u32(Bl) + off);
        }
#pragma unroll
        for (int mi = 0; mi < 2; mi++) {
#pragma unroll
            for (int p = 0; p < 4; p++) {
                mma16816(acc[mi][2 * p],     ah[mi], bh[p][0], bh[p][1]);
                mma16816(acc[mi][2 * p + 1], ah[mi], bh[p][2], bh[p][3]);
                mma16816(acc[mi][2 * p],     ah[mi], bl[p][0], bl[p][1]);
                mma16816(acc[mi][2 * p + 1], ah[mi], bl[p][2], bl[p][3]);
                mma16816(acc[mi][2 * p],     al[mi], bh[p][0], bh[p][1]);
                mma16816(acc[mi][2 * p + 1], al[mi], bh[p][2], bh[p][3]);
            }
        }
    }

#pragma unroll
    for (int mi = 0; mi < 2; mi++) {
#pragma unroll
        for (int nj = 0; nj < 8; nj++) {
            int m = m0 + wm0 + mi * 16 + (lane >> 2);
            int n = n0 + wn0 + nj * 8 + (lane & 3) * 2;
            if (n < NCLS) {
                float* c = acc[mi][nj];
                *(float2*)(out + (long)m * NCLS + n) =
                    make_float2(64.f * c[0], 64.f * c[1]);
                *(float2*)(out + (long)(m + 8) * NCLS + n) =
                    make_float2(64.f * c[2], 64.f * c[3]);
            }
        }
    }
}

// ---------------- ArcFace margin: exact fp32 target logit + margin ----------------
__global__ void margin_kernel(float* __restrict__ out, const int* __restrict__ gt,
                              const float* __restrict__ f32, const float* __restrict__ arc)
{
    const int r    = blockIdx.x * 4 + (threadIdx.x >> 5);
    const int lane = threadIdx.x & 31;
    if (r >= N_IMG) return;
    const int c = gt[r];
    float4 wv = __ldg((const float4*)(arc + (long)c * 128) + lane);
    float4 fv = *((const float4*)(f32 + (long)r * 128) + lane);
    float ws = wv.x * wv.x + wv.y * wv.y + wv.z * wv.z + wv.w * wv.w;
    float dt = wv.x * fv.x + wv.y * fv.y + wv.z * fv.z + wv.w * fv.w;
#pragma unroll
    for (int o = 16; o > 0; o >>= 1) {
        ws += __shfl_xor_sync(0xffffffffu, ws, o);
        dt += __shfl_xor_sync(0xffffffffu, dt, o);
    }
    if (lane == 0) {
        float t = dt / fmaxf(sqrtf(ws), 1e-12f);
        t = fminf(fmaxf(t, -1.f), 1.f);
        out[(long)r * NCLS + c] = 64.f * cosf(acosf(t) + 0.5f);
    }
}

// ---------------- launcher ----------------
extern "C" void kernel_launch(void* const* d_in, const int* in_sizes, int n_in,
                              void* d_out, int out_size)
{
    (void)in_sizes; (void)n_in; (void)out_size;
    const float* x   = (const float*)d_in[0];
    const int*   gt  = (const int*)d_in[1];
    const float* w1  = (const float*)d_in[2];
    const float* b1  = (const float*)d_in[3];
    const float* g1  = (const float*)d_in[4];
    const float* be1 = (const float*)d_in[5];
    const float* w2  = (const float*)d_in[6];
    const float* b2  = (const float*)d_in[7];
    const float* g2  = (const float*)d_in[8];
    const float* be2 = (const float*)d_in[9];
    const float* w3  = (const float*)d_in[10];
    const float* b3  = (const float*)d_in[11];
    const float* g3  = (const float*)d_in[12];
    const float* be3 = (const float*)d_in[13];
    const float* w4  = (const float*)d_in[14];
    const float* b4  = (const float*)d_in[15];
    const float* g4  = (const float*)d_in[16];
    const float* be4 = (const float*)d_in[17];
    const float* arc = (const float*)d_in[18];
    float* outp = (float*)d_out;

    float *y1, *y2, *y3, *y4, *f32, *part, *bns, *bnsh;
    __nv_bfloat16 *fhi, *flo, *whi, *wlo, *wt3h, *wt3l, *wt4h, *wt4l;
    cudaGetSymbolAddress((void**)&y1,   g_y1);
    cudaGetSymbolAddress((void**)&y2,   g_y2);
    cudaGetSymbolAddress((void**)&y3,   g_y3);
    cudaGetSymbolAddress((void**)&y4,   g_y4);
    cudaGetSymbolAddress((void**)&f32,  g_f32);
    cudaGetSymbolAddress((void**)&fhi,  g_fhi);
    cudaGetSymbolAddress((void**)&flo,  g_flo);
    cudaGetSymbolAddress((void**)&whi,  g_whi);
    cudaGetSymbolAddress((void**)&wlo,  g_wlo);
    cudaGetSymbolAddress((void**)&wt3h, g_wt3h);
    cudaGetSymbolAddress((void**)&wt3l, g_wt3l);
    cudaGetSymbolAddress((void**)&wt4h, g_wt4h);
    cudaGetSymbolAddress((void**)&wt4l, g_wt4l);
    cudaGetSymbolAddress((void**)&part, g_part);
    cudaGetSymbolAddress((void**)&bns,  g_bns);
    cudaGetSymbolAddress((void**)&bnsh, g_bnsh);

    // weight pre-transpose for HMMA convs
    prep_w<32, 64><<<(9 * 64 * 32 + 255) / 256, 256>>>(w3, wt3h, wt3l);
    prep_w<64, 128><<<(9 * 128 * 64 + 255) / 256, 256>>>(w4, wt4h, wt4l);

    // layer 1: conv(1->16, 4x4, s2, p1) 112 -> 56  (direct FFMA2)
    conv_fwd<1, 16, 16, 4, 4, 2, 1, 112, 112, 56, 56, false>
        <<<3136, 256>>>(x, w1, b1, nullptr, nullptr, y1);
    stats_partial<<<dim3(16, 64), 256>>>(y1, 16, 3136, part);
    stats_final<<<16, 64>>>(part, 1.f / (512.f * 3136.f), g1, be1, bns + 0, bnsh + 0);

    // layer 2: conv(16->32, 4x4, s2, p1) 56 -> 28  (direct FFMA2)
    conv_fwd<16, 32, 32, 4, 4, 2, 1, 56, 56, 28, 28, true>
        <<<dim3(784, 1), 256>>>(y1, w2, b2, bns + 0, bnsh + 0, y2);
    stats_partial<<<dim3(32, 64), 256>>>(y2, 32, 784, part);
    stats_final<<<32, 64>>>(part, 1.f / (512.f * 784.f), g2, be2, bns + 128, bnsh + 128);

    // layer 3: conv(32->64, 3x3, s1, p0) 28 -> 26  (HMMA implicit GEMM)
    {
        constexpr int INP_B = 12 * 28 * 40 * 2;
        constexpr int WTAP_B = 64 * 40 * 2;
        constexpr int S3 = 2 * INP_B + 4 * WTAP_B + (64 + 2 * 32) * 4;
        cudaFuncSetAttribute(conv_hmma<32, 64, 28, 28, 26, 26, 12>,
                             cudaFuncAttributeMaxDynamicSharedMemorySize, S3);
        conv_hmma<32, 64, 28, 28, 26, 26, 12>
            <<<dim3(4, 512), 256, S3>>>(y2, wt3h, wt3l, b3, bns + 128, bnsh + 128, y3);
    }
    stats_partial<<<dim3(64, 64), 256>>>(y3, 64, 676, part);
    stats_final<<<64, 64>>>(part, 1.f / (512.f * 676.f), g3, be3, bns + 256, bnsh + 256);

    // layer 4: conv(64->128, 3x3, s1, p0) 26 -> 24  (HMMA implicit GEMM)
    {
        constexpr int INP_B = 10 * 26 * 72 * 2;
        constexpr int WTAP_B = 128 * 72 * 2;
        constexpr int S4 = 2 * INP_B + 4 * WTAP_B + (128 + 2 * 64) * 4;
        cudaFuncSetAttribute(conv_hmma<64, 128, 26, 26, 24, 24, 10>,
                             cudaFuncAttributeMaxDynamicSharedMemorySize, S4);
        conv_hmma<64, 128, 26, 26, 24, 24, 10>
            <<<dim3(3, 512), 256, S4>>>(y3, wt4h, wt4l, b4, bns + 256, bnsh + 256, y4);
    }
    stats_partial<<<dim3(128, 64), 256>>>(y4, 128, 576, part);
    stats_final<<<128, 64>>>(part, 1.f / (512.f * 576.f), g4, be4, bns + 384, bnsh + 384);

    // GAP (+BN+ReLU fused) + feature normalize (+fp32 copy) + bf16 split
    gap_norm<<<512, 128>>>(y4, bns + 384, bnsh + 384, f32, fhi, flo);

    // arc weight row normalize + bf16 split
    wnorm_split<<<12500, 256>>>(arc, whi, wlo);

    // split-bf16 HMMA cosine GEMM (scaled by 64); m-tile fastest for B L2 reuse
    cudaFuncSetAttribute(arc_gemm, cudaFuncAttributeMaxDynamicSharedMemorySize, 4 * GT_BYTES);
    arc_gemm<<<dim3(4, (NCLS + 127) / 128), 256, 4 * GT_BYTES>>>(fhi, flo, whi, wlo, outp);

    // exact margin scatter (fp32 recompute; overwrites target entries)
    margin_kernel<<<128, 128>>>(outp, gt, f32, arc);
}

// round 14
// speedup vs baseline: 1.5792x; 1.0843x over previous
#include <cuda_runtime.h>
#include <cuda_bf16.h>
#include <stdint.h>
#include <math.h>

#define N_IMG 512
#define NCLS  100000

// ---------------- scratch (static device globals; no allocation) ----------------
__device__ float g_y1[512 * 16 * 56 * 56];
__device__ float g_y2[512 * 32 * 28 * 28];
__device__ float g_y3[512 * 64 * 26 * 26];
__device__ float g_y4[512 * 128 * 24 * 24];
__device__ float g_f32[512 * 128];
__device__ __nv_bfloat16 g_fhi[512 * 128];
__device__ __nv_bfloat16 g_flo[512 * 128];
__device__ __nv_bfloat16 g_whi[100000 * 128];
__device__ __nv_bfloat16 g_wlo[100000 * 128];
__device__ __nv_bfloat16 g_wt3h[9 * 64 * 32];
__device__ __nv_bfloat16 g_wt3l[9 * 64 * 32];
__device__ __nv_bfloat16 g_wt4h[9 * 128 * 64];
__device__ __nv_bfloat16 g_wt4l[9 * 128 * 64];
__device__ float g_part[128 * 64 * 2];
__device__ float g_bns[4 * 128];
__device__ float g_bnsh[4 * 128];

// ---------------- packed f32x2 helpers ----------------
__device__ __forceinline__ unsigned long long pack_dup(float x) {
    unsigned long long r; asm("mov.b64 %0,{%1,%1};" : "=l"(r) : "f"(x)); return r;
}
__device__ __forceinline__ unsigned long long pack2(float x, float y) {
    unsigned long long r; asm("mov.b64 %0,{%1,%2};" : "=l"(r) : "f"(x), "f"(y)); return r;
}
__device__ __forceinline__ unsigned long long ffma2(unsigned long long a, unsigned long long b,
                                                    unsigned long long c) {
    unsigned long long d;
    asm("fma.rn.f32x2 %0,%1,%2,%3;" : "=l"(d) : "l"(a), "l"(b), "l"(c));
    return d;
}
__device__ __forceinline__ float2 unpack2(unsigned long long v) {
    float2 f; asm("mov.b64 {%0,%1},%2;" : "=f"(f.x), "=f"(f.y) : "l"(v)); return f;
}

// ---------------- warp-mma helpers ----------------
__device__ __forceinline__ uint32_t smem_u32(const void* p) {
    uint32_t a;
    asm("{ .reg .u64 t; cvta.to.shared.u64 t, %1; cvt.u32.u64 %0, t; }" : "=r"(a) : "l"(p));
    return a;
}
__device__ __forceinline__ void ldsm4(uint32_t* r, uint32_t a) {
    asm volatile("ldmatrix.sync.aligned.m8n8.x4.shared.b16 {%0,%1,%2,%3}, [%4];"
                 : "=r"(r[0]), "=r"(r[1]), "=r"(r[2]), "=r"(r[3]) : "r"(a));
}
__device__ __forceinline__ void mma16816(float* c, const uint32_t* a, uint32_t b0, uint32_t b1) {
    asm volatile(
        "mma.sync.aligned.m16n8k16.row.col.f32.bf16.bf16.f32 "
        "{%0,%1,%2,%3}, {%4,%5,%6,%7}, {%8,%9}, {%0,%1,%2,%3};"
        : "+f"(c[0]), "+f"(c[1]), "+f"(c[2]), "+f"(c[3])
        : "r"(a[0]), "r"(a[1]), "r"(a[2]), "r"(a[3]), "r"(b0), "r"(b1));
}

// ---------------- direct conv (conv1 / conv2 only) ----------------
template <int CIN, int COUT, int COUTB, int KH, int KW, int STR, int PAD,
          int IH, int IW, int OH, int OW, bool INBN>
__global__ void __launch_bounds__(256, 2) conv_fwd(
    const float* __restrict__ in, const float* __restrict__ wgl,
    const float* __restrict__ bias,
    const float* __restrict__ isc, const float* __restrict__ ish,
    float* __restrict__ out)
{
    constexpr int TAPS  = KH * KW;
    constexpr int NPAIR = COUTB / 2;
    constexpr int PW    = KW + STR;
    constexpr int PPR   = OW / 2;
    constexpr int NPX   = OH * PPR;

    __shared__ __align__(16) float wsm[CIN * TAPS * COUTB];
    __shared__ float bsm[COUTB];
    __shared__ float scsm[CIN], shsm[CIN];

    const int tid = threadIdx.x;
    const int cg  = blockIdx.y;

    for (int i = tid; i < CIN * TAPS * COUTB; i += 256) {
        int co  = i % COUTB;
        int tap = (i / COUTB) % TAPS;
        int ci  = i / (COUTB * TAPS);
        wsm[i] = wgl[((cg * COUTB + co) * CIN + ci) * TAPS + tap];
    }
    if (tid < COUTB) bsm[tid] = bias[cg * COUTB + tid];
    if (INBN) {
        for (int i = tid; i < CIN; i += 256) { scsm[i] = isc[i]; shsm[i] = ish[i]; }
    }
    __syncthreads();

    const int gid = blockIdx.x * 256 + tid;
    if (gid >= N_IMG * NPX) return;
    const int n   = gid / NPX;
    const int r   = gid % NPX;
    const int oh  = r / PPR;
    const int ow0 = (r % PPR) * 2;

    unsigned long long acc[2][NPAIR];
#pragma unroll
    for (int p = 0; p < NPAIR; p++) {
        unsigned long long b = pack2(bsm[2 * p], bsm[2 * p + 1]);
        acc[0][p] = b; acc[1][p] = b;
    }

    const float* img = in + (long)n * CIN * IH * IW;
    const int ih0 = oh * STR - PAD;
    const int iw0 = ow0 * STR - PAD;

    for (int ci = 0; ci < CIN; ci++) {
        const float* cp = img + ci * IH * IW;
        float sc = INBN ? scsm[ci] : 0.f;
        float sh = INBN ? shsm[ci] : 0.f;
        float pd[KH][PW];
#pragma unroll
        for (int rr = 0; rr < KH; rr++) {
            int ih = ih0 + rr;
#pragma unroll
            for (int cc = 0; cc < PW; cc++) {
                int iw = iw0 + cc;
                float v = 0.f;
                if (PAD == 0 || ((unsigned)ih < (unsigned)IH && (unsigned)iw < (unsigned)IW))
                    v = __ldg(cp + ih * IW + iw);
                if (INBN) v = fmaxf(fmaf(v, sc, sh), 0.f);
                pd[rr][cc] = v;
            }
        }
        const float* wc = wsm + ci * TAPS * COUTB;
#pragma unroll
        for (int rr = 0; rr < KH; rr++) {
#pragma unroll
            for (int q = 0; q < KW; q++) {
                const ulonglong2* wp = (const ulonglong2*)(wc + (rr * KW + q) * COUTB);
                unsigned long long p0 = pack_dup(pd[rr][q]);
                unsigned long long p1 = pack_dup(pd[rr][q + STR]);
#pragma unroll
                for (int p2 = 0; p2 < NPAIR / 2; p2++) {
                    ulonglong2 w = wp[p2];
                    acc[0][2 * p2]     = ffma2(p0, w.x, acc[0][2 * p2]);
                    acc[1][2 * p2]     = ffma2(p1, w.x, acc[1][2 * p2]);
                    acc[0][2 * p2 + 1] = ffma2(p0, w.y, acc[0][2 * p2 + 1]);
                    acc[1][2 * p2 + 1] = ffma2(p1, w.y, acc[1][2 * p2 + 1]);
                }
            }
        }
    }

    float* op = out + (((long)n * COUT + cg * COUTB) * OH + oh) * OW + ow0;
#pragma unroll
    for (int p = 0; p < NPAIR; p++) {
        float2 a0 = unpack2(acc[0][p]);
        float2 a1 = unpack2(acc[1][p]);
        *(float2*)(op + (2 * p)     * OH * OW) = make_float2(a0.x, a1.x);
        *(float2*)(op + (2 * p + 1) * OH * OW) = make_float2(a0.y, a1.y);
    }
}

// ---------------- weight pre-transpose + bf16 split: [co][ci][tap] -> [tap][co][ci]
template <int CIN, int COUT>
__global__ void prep_w(const float* __restrict__ w,
                       __nv_bfloat16* __restrict__ wh, __nv_bfloat16* __restrict__ wl)
{
    int i = blockIdx.x * 256 + threadIdx.x;
    if (i >= 9 * COUT * CIN) return;
    int ci = i % CIN;
    int co = (i / CIN) % COUT;
    int t  = i / (CIN * COUT);
    float v = __ldg(w + ((size_t)co * CIN + ci) * 9 + t);
    __nv_bfloat16 h = __float2bfloat16(v);
    wh[i] = h;
    wl[i] = __float2bfloat16(v - __bfloat162float(h));
}

// ---------------- HMMA implicit-GEMM conv (3x3, stride 1, pad 0) ----------------
template <int CIN, int COUT, int IW_, int IH_, int OW_, int OH_, int RT, int MINB>
__global__ void __launch_bounds__(256, MINB) conv_hmma(
    const float* __restrict__ in,
    const __nv_bfloat16* __restrict__ wth, const __nv_bfloat16* __restrict__ wtl,
    const float* __restrict__ bias,
    const float* __restrict__ isc, const float* __restrict__ ish,
    float* __restrict__ out)
{
    constexpr int MT     = 192;
    constexpr int PADCI  = CIN + 8;
    constexpr int WN     = COUT / 2;
    constexpr int NP     = WN / 16;
    constexpr int KS     = CIN / 16;
    constexpr int NPX_T  = RT * IW_;
    constexpr int INP_B  = NPX_T * PADCI * 2;
    constexpr int WTAP_B = COUT * PADCI * 2;
    constexpr int CH     = COUT * (CIN / 8);

    extern __shared__ __align__(16) char sm[];
    __nv_bfloat16* inp_h = (__nv_bfloat16*)(sm);
    __nv_bfloat16* inp_l = (__nv_bfloat16*)(sm + INP_B);
    char*  wb     = sm + 2 * INP_B;
    float* bias_s = (float*)(sm + 2 * INP_B + 4 * WTAP_B);
    float* sc_s   = bias_s + COUT;
    float* sh_s   = sc_s + CIN;

    const int tid  = threadIdx.x;
    const int wid  = tid >> 5, lane = tid & 31;
    const int wm   = wid & 3,  wn   = wid >> 2;
    const int nimg = blockIdx.y;
    const int m0   = blockIdx.x * MT;
    const int r_lo = m0 / OW_;

    for (int i = tid; i < COUT; i += 256) bias_s[i] = bias[i];
    for (int i = tid; i < CIN;  i += 256) { sc_s[i] = isc[i]; sh_s[i] = ish[i]; }
    __syncthreads();

    const float* imgp = in + (size_t)nimg * CIN * IH_ * IW_;
    for (int i = tid; i < NPX_T * CIN; i += 256) {
        int px = i % NPX_T, ci = i / NPX_T;
        int row = r_lo + px / IW_; if (row > IH_ - 1) row = IH_ - 1;
        int col = px % IW_;
        float v = __ldg(imgp + ci * IH_ * IW_ + row * IW_ + col);
        v = fmaxf(fmaf(v, sc_s[ci], sh_s[ci]), 0.f);
        __nv_bfloat16 h = __float2bfloat16(v);
        inp_h[px * PADCI + ci] = h;
        inp_l[px * PADCI + ci] = __float2bfloat16(v - __bfloat162float(h));
    }

    auto issue_tap = [&](int t, int buf) {
        uint32_t d_h = smem_u32(wb + (buf * 2 + 0) * WTAP_B);
        uint32_t d_l = smem_u32(wb + (buf * 2 + 1) * WTAP_B);
        const __nv_bfloat16* s_h = wth + (size_t)t * COUT * CIN;
        const __nv_bfloat16* s_l = wtl + (size_t)t * COUT * CIN;
        for (int j = tid; j < CH; j += 256) {
            int co = j / (CIN / 8), seg = j % (CIN / 8);
            uint32_t doff = (uint32_t)(co * PADCI + seg * 8) * 2;
            size_t   soff = (size_t)co * CIN + seg * 8;
            asm volatile("cp.async.cg.shared.global [%0], [%1], 16;"
                         :: "r"(d_h + doff), "l"(s_h + soff) : "memory");
            asm volatile("cp.async.cg.shared.global [%0], [%1], 16;"
                         :: "r"(d_l + doff), "l"(s_l + soff) : "memory");
        }
        asm volatile("cp.async.commit_group;" ::: "memory");
    };
    issue_tap(0, 0);

    int tr0[3], cc0[3];
#pragma unroll
    for (int mi = 0; mi < 3; mi++) {
        int mg = m0 + wm * 48 + mi * 16 + (lane & 15);
        int rr = mg / OW_;
        tr0[mi] = rr - r_lo;
        cc0[mi] = mg - rr * OW_;
    }
    const int acol8 = ((lane >> 4) & 1) * 8;
    const int brow  = ((lane >> 4) & 1) * 8 + (lane & 7);
    const int bcol8 = ((lane >> 3) & 1) * 8;

    float acc[3][2 * NP][4];
#pragma unroll
    for (int a = 0; a < 3; a++)
#pragma unroll
        for (int b = 0; b < 2 * NP; b++)
#pragma unroll
            for (int q = 0; q < 4; q++) acc[a][b][q] = 0.f;

    const uint32_t ih_b = smem_u32(inp_h), il_b = smem_u32(inp_l);

    for (int t = 0; t < 9; t++) {
        __syncthreads();
        if (t < 8) {
            issue_tap(t + 1, (t + 1) & 1);
            asm volatile("cp.async.wait_group 1;" ::: "memory");
        } else {
            asm volatile("cp.async.wait_group 0;" ::: "memory");
        }
        __syncthreads();

        const int dr = t / 3, dc = t - dr * 3;
        const uint32_t wh_b = smem_u32(wb + ((t & 1) * 2 + 0) * WTAP_B);
        const uint32_t wl_b = smem_u32(wb + ((t & 1) * 2 + 1) * WTAP_B);

#pragma unroll
        for (int ks = 0; ks < KS; ks++) {
            const int k0 = ks * 16;
            uint32_t ah[3][4], al[3][4], bh[NP][4], bl[NP][4];
#pragma unroll
            for (int mi = 0; mi < 3; mi++) {
                int tr = tr0[mi] + dr; if (tr > RT - 1) tr = RT - 1;
                uint32_t off = (uint32_t)((tr * IW_ + cc0[mi] + dc) * PADCI + k0 + acol8) * 2;
                ldsm4(ah[mi], ih_b + off);
                ldsm4(al[mi], il_b + off);
            }
#pragma unroll
            for (int p = 0; p < NP; p++) {
                uint32_t off = (uint32_t)((wn * WN + p * 16 + brow) * PADCI + k0 + bcol8) * 2;
                ldsm4(bh[p], wh_b + off);
                ldsm4(bl[p], wl_b + off);
            }
#pragma unroll
            for (int mi = 0; mi < 3; mi++)
#pragma unroll
                for (int p = 0; p < NP; p++) {
                    mma16816(acc[mi][2 * p],     ah[mi], bh[p][0], bh[p][1]);
                    mma16816(acc[mi][2 * p + 1], ah[mi], bh[p][2], bh[p][3]);
                    mma16816(acc[mi][2 * p],     ah[mi], bl[p][0], bl[p][1]);
                    mma16816(acc[mi][2 * p + 1], ah[mi], bl[p][2], bl[p][3]);
                    mma16816(acc[mi][2 * p],     al[mi], bh[p][0], bh[p][1]);
                    mma16816(acc[mi][2 * p + 1], al[mi], bh[p][2], bh[p][3]);
                }
        }
    }

    const size_t obase = (size_t)nimg * COUT * OH_ * OW_;
#pragma unroll
    for (int mi = 0; mi < 3; mi++) {
        int pxa = m0 + wm * 48 + mi * 16 + (lane >> 2);
#pragma unroll
        for (int nj = 0; nj < 2 * NP; nj++) {
            int co = wn * WN + nj * 8 + (lane & 3) * 2;
            float b0 = bias_s[co], b1 = bias_s[co + 1];
            if (pxa < OH_ * OW_) {
                out[obase + (size_t)co * OH_ * OW_ + pxa]       = acc[mi][nj][0] + b0;
                out[obase + (size_t)(co + 1) * OH_ * OW_ + pxa] = acc[mi][nj][1] + b1;
            }
            int pxb = pxa + 8;
            if (pxb < OH_ * OW_) {
                out[obase + (size_t)co * OH_ * OW_ + pxb]       = acc[mi][nj][2] + b0;
                out[obase + (size_t)(co + 1) * OH_ * OW_ + pxb] = acc[mi][nj][3] + b1;
            }
        }
    }
}

// ---------------- BN statistics: coalesced float4 streaming, no divisions -------
__global__ void __launch_bounds__(256) stats_partial(const float* __restrict__ y,
                                                     int C, int plane,
                                                     float* __restrict__ part)
{
    const int c     = blockIdx.x;
    const int tid   = threadIdx.x;
    const int n0    = blockIdx.y * 8;
    const int pv    = plane >> 2;
    __shared__ float ss[256], s2[256];

    float a = 0.f, b = 0.f;
#pragma unroll 1
    for (int n = n0; n < n0 + 8; n++) {
        const float4* p = (const float4*)(y + ((long)n * C + c) * plane);
        for (int i = tid; i < pv; i += 256) {
            float4 v = __ldg(p + i);
            a += v.x + v.y + v.z + v.w;
            b += v.x * v.x + v.y * v.y + v.z * v.z + v.w * v.w;
        }
    }
    ss[tid] = a; s2[tid] = b;
    __syncthreads();
    for (int s = 128; s > 0; s >>= 1) {
        if (tid < s) { ss[tid] += ss[tid + s]; s2[tid] += s2[tid + s]; }
        __syncthreads();
    }
    if (tid == 0) {
        part[(c * 64 + blockIdx.y) * 2 + 0] = ss[0];
        part[(c * 64 + blockIdx.y) * 2 + 1] = s2[0];
    }
}

__global__ void stats_final(const float* __restrict__ part, float invM,
                            const float* __restrict__ g, const float* __restrict__ be,
                            float* __restrict__ sc, float* __restrict__ sh)
{
    const int c = blockIdx.x, t = threadIdx.x;
    __shared__ float ss[64], s2[64];
    ss[t] = part[(c * 64 + t) * 2 + 0];
    s2[t] = part[(c * 64 + t) * 2 + 1];
    __syncthreads();
    for (int s = 32; s > 0; s >>= 1) {
        if (t < s) { ss[t] += ss[t + s]; s2[t] += s2[t + s]; }
        __syncthreads();
    }
    if (t == 0) {
        float mu    = ss[0] * invM;
        float var   = fmaxf(s2[0] * invM - mu * mu, 0.f);
        float scale = g[c] * rsqrtf(var + 1e-5f);
        sc[c] = scale;
        sh[c] = be[c] - mu * scale;
    }
}

// ---------------- GAP (fused BN+ReLU) + L2 normalize + bf16 split ----------------
__global__ void gap_norm(const float* __restrict__ y4, const float* __restrict__ sc,
                         const float* __restrict__ sh, float* __restrict__ f32,
                         __nv_bfloat16* __restrict__ fhi, __nv_bfloat16* __restrict__ flo)
{
    const int n = blockIdx.x, c = threadIdx.x;   // 128 threads
    const float4* p = (const float4*)(y4 + ((long)n * 128 + c) * 576);
    const float scale = sc[c], shift = sh[c];
    float s = 0.f;
#pragma unroll 4
    for (int i = 0; i < 144; i++) {
        float4 v = __ldg(p + i);
        s += fmaxf(fmaf(v.x, scale, shift), 0.f) + fmaxf(fmaf(v.y, scale, shift), 0.f)
           + fmaxf(fmaf(v.z, scale, shift), 0.f) + fmaxf(fmaf(v.w, scale, shift), 0.f);
    }
    float f = s * (1.f / 576.f);
    __shared__ float sq[128];
    sq[c] = f * f;
    __syncthreads();
    for (int st = 64; st > 0; st >>= 1) {
        if (c < st) sq[c] += sq[c + st];
        __syncthreads();
    }
    float inv = 1.f / fmaxf(sqrtf(sq[0]), 1e-12f);
    float v = f * inv;
    f32[n * 128 + c] = v;
    __nv_bfloat16 h = __float2bfloat16(v);
    fhi[n * 128 + c] = h;
    flo[n * 128 + c] = __float2bfloat16(v - __bfloat162float(h));
}

// ---------------- ArcFace weight row normalization + bf16 split ----------------
__global__ void wnorm_split(const float* __restrict__ w,
                            __nv_bfloat16* __restrict__ whi, __nv_bfloat16* __restrict__ wlo)
{
    const int row  = blockIdx.x * 8 + (threadIdx.x >> 5);
    const int lane = threadIdx.x & 31;
    if (row >= NCLS) return;
    float4 v = __ldg((const float4*)(w + (long)row * 128) + lane);
    float s = v.x * v.x + v.y * v.y + v.z * v.z + v.w * v.w;
#pragma unroll
    for (int o = 16; o > 0; o >>= 1) s += __shfl_xor_sync(0xffffffffu, s, o);
    float inv = 1.f / fmaxf(sqrtf(s), 1e-12f);
    float n0 = v.x * inv, n1 = v.y * inv, n2 = v.z * inv, n3 = v.w * inv;
    __nv_bfloat16 h0 = __float2bfloat16(n0), h1 = __float2bfloat16(n1);
    __nv_bfloat16 h2 = __float2bfloat16(n2), h3 = __float2bfloat16(n3);
    __nv_bfloat162 hp0; hp0.x = h0; hp0.y = h1;
    __nv_bfloat162 hp1; hp1.x = h2; hp1.y = h3;
    __nv_bfloat162 lp0;
    lp0.x = __float2bfloat16(n0 - __bfloat162float(h0));
    lp0.y = __float2bfloat16(n1 - __bfloat162float(h1));
    __nv_bfloat162 lp1;
    lp1.x = __float2bfloat16(n2 - __bfloat162float(h2));
    lp1.y = __float2bfloat16(n3 - __bfloat162float(h3));
    *(__nv_bfloat162*)(whi + (long)row * 128 + lane * 4)     = hp0;
    *(__nv_bfloat162*)(whi + (long)row * 128 + lane * 4 + 2) = hp1;
    *(__nv_bfloat162*)(wlo + (long)row * 128 + lane * 4)     = lp0;
    *(__nv_bfloat162*)(wlo + (long)row * 128 + lane * 4 + 2) = lp1;
}

// ---------------- split-bf16 cosine GEMM via mma.sync (HMMA), persistent --------
// grid (4, 37): 148 CTAs, one wave. Each CTA: fixed m-tile (A resident in smem),
// walks n-tiles j = by, by+37, ... with double-buffered B prefetch via cp.async.
#define GSTR 136
#define GT_BYTES (128 * GSTR * 2)     // 34816 per half-tile
#define NT_TILES ((NCLS + 127) / 128) // 782
#define NT_STRIDE 37

__global__ void __launch_bounds__(256) arc_gemm(
    const __nv_bfloat16* __restrict__ fhi, const __nv_bfloat16* __restrict__ flo,
    const __nv_bfloat16* __restrict__ whi, const __nv_bfloat16* __restrict__ wlo,
    float* __restrict__ out)
{
    extern __shared__ __align__(16) char sm[];
    __nv_bfloat16* Ah = (__nv_bfloat16*)(sm);
    __nv_bfloat16* Al = (__nv_bfloat16*)(sm + GT_BYTES);
    char* Bbase = sm + 2 * GT_BYTES;   // [buf][hi|lo] x GT_BYTES  (4 x 34816)

    const int tid  = threadIdx.x;
    const int wid  = tid >> 5, lane = tid & 31;
    const int m0   = blockIdx.x * 128;
    const int wm0  = (wid & 3) * 32;
    const int wn0  = (wid >> 2) * 64;

    // B prefetch: cp.async 16B chunks; OOB class rows -> src-size 0 (zero fill)
    auto issueB = [&](int ntile, int buf) {
        uint32_t dh = smem_u32(Bbase + (buf * 2 + 0) * GT_BYTES);
        uint32_t dl = smem_u32(Bbase + (buf * 2 + 1) * GT_BYTES);
        for (int i = tid; i < 128 * 16; i += 256) {
            int row = i >> 4, seg = i & 15;
            int cls = ntile * 128 + row;
            uint32_t doff = (uint32_t)(row * GSTR + seg * 8) * 2;
            size_t   soff = (size_t)cls * 128 + seg * 8;
            int sz = (cls < NCLS) ? 16 : 0;
            asm volatile("cp.async.cg.shared.global [%0], [%1], 16, %2;"
                         :: "r"(dh + doff), "l"(whi + soff), "r"(sz) : "memory");
            asm volatile("cp.async.cg.shared.global [%0], [%1], 16, %2;"
                         :: "r"(dl + doff), "l"(wlo + soff), "r"(sz) : "memory");
        }
        asm volatile("cp.async.commit_group;" ::: "memory");
    };

    // kick off first B tile, then stage A (overlaps with B's flight)
    issueB(blockIdx.y, 0);
    for (int i = tid; i < 128 * 16; i += 256) {
        int row = i >> 4, seg = (i & 15) << 3;
        uint4 vh = *(const uint4*)(fhi + (long)(m0 + row) * 128 + seg);
        uint4 vl = *(const uint4*)(flo + (long)(m0 + row) * 128 + seg);
        *(uint4*)(Ah + row * GSTR + seg) = vh;
        *(uint4*)(Al + row * GSTR + seg) = vl;
    }

    const int arow = lane & 15, acol8 = (lane >> 4) & 1;
    const int brow = ((lane >> 4) & 1) * 8 + (lane & 7);
    const int bcol8 = (lane >> 3) & 1;
    const uint32_t Ah_b = smem_u32(Ah), Al_b = smem_u32(Al);

    int k = 0;
    for (int j = blockIdx.y; j < NT_TILES; j += NT_STRIDE, k++) {
        asm volatile("cp.async.wait_group 0;" ::: "memory");
        __syncthreads();                         // B[k&1] + A visible; old buf reads done
        if (j + NT_STRIDE < NT_TILES)
            issueB(j + NT_STRIDE, (k + 1) & 1);  // prefetch next while computing

        const uint32_t Bh_b = smem_u32(Bbase + ((k & 1) * 2 + 0) * GT_BYTES);
        const uint32_t Bl_b = smem_u32(Bbase + ((k & 1) * 2 + 1) * GT_BYTES);
        const int n0 = j * 128;

        float acc[2][8][4];
#pragma unroll
        for (int i = 0; i < 2; i++)
#pragma unroll
            for (int jj = 0; jj < 8; jj++)
#pragma unroll
                for (int q = 0; q < 4; q++) acc[i][jj][q] = 0.f;

#pragma unroll
        for (int ks = 0; ks < 8; ks++) {
            const int k0 = ks * 16;
            uint32_t ah[2][4], al[2][4], bh[4][4], bl[4][4];
#pragma unroll
            for (int mi = 0; mi < 2; mi++) {
                uint32_t off = ((wm0 + mi * 16 + arow) * GSTR + k0 + acol8 * 8) * 2;
                ldsm4(ah[mi], Ah_b + off);
                ldsm4(al[mi], Al_b + off);
            }
#pragma unroll
            for (int p = 0; p < 4; p++) {
                uint32_t off = ((wn0 + p * 16 + brow) * GSTR + k0 + bcol8 * 8) * 2;
                ldsm4(bh[p], Bh_b + off);
                ldsm4(bl[p], Bl_b + off);
            }
#pragma unroll
            for (int mi = 0; mi < 2; mi++) {
#pragma unroll
                for (int p = 0; p < 4; p++) {
                    mma16816(acc[mi][2 * p],     ah[mi], bh[p][0], bh[p][1]);
                    mma16816(acc[mi][2 * p + 1], ah[mi], bh[p][2], bh[p][3]);
                    mma16816(acc[mi][2 * p],     ah[mi], bl[p][0], bl[p][1]);
                    mma16816(acc[mi][2 * p + 1], ah[mi], bl[p][2], bl[p][3]);
                    mma16816(acc[mi][2 * p],     al[mi], bh[p][0], bh[p][1]);
                    mma16816(acc[mi][2 * p + 1], al[mi], bh[p][2], bh[p][3]);
                }
            }
        }

#pragma unroll
        for (int mi = 0; mi < 2; mi++) {
#pragma unroll
            for (int nj = 0; nj < 8; nj++) {
                int m = m0 + wm0 + mi * 16 + (lane >> 2);
                int n = n0 + wn0 + nj * 8 + (lane & 3) * 2;
                if (n < NCLS) {
                    float* c = acc[mi][nj];
                    *(float2*)(out + (long)m * NCLS + n) =
                        make_float2(64.f * c[0], 64.f * c[1]);
                    *(float2*)(out + (long)(m + 8) * NCLS + n) =
                        make_float2(64.f * c[2], 64.f * c[3]);
                }
            }
        }
    }
}

// ---------------- ArcFace margin: exact fp32 target logit + margin ----------------
__global__ void margin_kernel(float* __restrict__ out, const int* __restrict__ gt,
                              const float* __restrict__ f32, const float* __restrict__ arc)
{
    const int r    = blockIdx.x * 4 + (threadIdx.x >> 5);
    const int lane = threadIdx.x & 31;
    if (r >= N_IMG) return;
    const int c = gt[r];
    float4 wv = __ldg((const float4*)(arc + (long)c * 128) + lane);
    float4 fv = *((const float4*)(f32 + (long)r * 128) + lane);
    float ws = wv.x * wv.x + wv.y * wv.y + wv.z * wv.z + wv.w * wv.w;
    float dt = wv.x * fv.x + wv.y * fv.y + wv.z * fv.z + wv.w * fv.w;
#pragma unroll
    for (int o = 16; o > 0; o >>= 1) {
        ws += __shfl_xor_sync(0xffffffffu, ws, o);
        dt += __shfl_xor_sync(0xffffffffu, dt, o);
    }
    if (lane == 0) {
        float t = dt / fmaxf(sqrtf(ws), 1e-12f);
        t = fminf(fmaxf(t, -1.f), 1.f);
        out[(long)r * NCLS + c] = 64.f * cosf(acosf(t) + 0.5f);
    }
}

// ---------------- launcher ----------------
extern "C" void kernel_launch(void* const* d_in, const int* in_sizes, int n_in,
                              void* d_out, int out_size)
{
    (void)in_sizes; (void)n_in; (void)out_size;
    const float* x   = (const float*)d_in[0];
    const int*   gt  = (const int*)d_in[1];
    const float* w1  = (const float*)d_in[2];
    const float* b1  = (const float*)d_in[3];
    const float* g1  = (const float*)d_in[4];
    const float* be1 = (const float*)d_in[5];
    const float* w2  = (const float*)d_in[6];
    const float* b2  = (const float*)d_in[7];
    const float* g2  = (const float*)d_in[8];
    const float* be2 = (const float*)d_in[9];
    const float* w3  = (const float*)d_in[10];
    const float* b3  = (const float*)d_in[11];
    const float* g3  = (const float*)d_in[12];
    const float* be3 = (const float*)d_in[13];
    const float* w4  = (const float*)d_in[14];
    const float* b4  = (const float*)d_in[15];
    const float* g4  = (const float*)d_in[16];
    const float* be4 = (const float*)d_in[17];
    const float* arc = (const float*)d_in[18];
    float* outp = (float*)d_out;

    float *y1, *y2, *y3, *y4, *f32, *part, *bns, *bnsh;
    __nv_bfloat16 *fhi, *flo, *whi, *wlo, *wt3h, *wt3l, *wt4h, *wt4l;
    cudaGetSymbolAddress((void**)&y1,   g_y1);
    cudaGetSymbolAddress((void**)&y2,   g_y2);
    cudaGetSymbolAddress((void**)&y3,   g_y3);
    cudaGetSymbolAddress((void**)&y4,   g_y4);
    cudaGetSymbolAddress((void**)&f32,  g_f32);
    cudaGetSymbolAddress((void**)&fhi,  g_fhi);
    cudaGetSymbolAddress((void**)&flo,  g_flo);
    cudaGetSymbolAddress((void**)&whi,  g_whi);
    cudaGetSymbolAddress((void**)&wlo,  g_wlo);
    cudaGetSymbolAddress((void**)&wt3h, g_wt3h);
    cudaGetSymbolAddress((void**)&wt3l, g_wt3l);
    cudaGetSymbolAddress((void**)&wt4h, g_wt4h);
    cudaGetSymbolAddress((void**)&wt4l, g_wt4l);
    cudaGetSymbolAddress((void**)&part, g_part);
    cudaGetSymbolAddress((void**)&bns,  g_bns);
    cudaGetSymbolAddress((void**)&bnsh, g_bnsh);

    // weight pre-transpose for HMMA convs
    prep_w<32, 64><<<(9 * 64 * 32 + 255) / 256, 256>>>(w3, wt3h, wt3l);
    prep_w<64, 128><<<(9 * 128 * 64 + 255) / 256, 256>>>(w4, wt4h, wt4l);

    // layer 1: conv(1->16, 4x4, s2, p1) 112 -> 56  (direct FFMA2)
    conv_fwd<1, 16, 16, 4, 4, 2, 1, 112, 112, 56, 56, false>
        <<<3136, 256>>>(x, w1, b1, nullptr, nullptr, y1);
    stats_partial<<<dim3(16, 64), 256>>>(y1, 16, 3136, part);
    stats_final<<<16, 64>>>(part, 1.f / (512.f * 3136.f), g1, be1, bns + 0, bnsh + 0);

    // layer 2: conv(16->32, 4x4, s2, p1) 56 -> 28  (direct FFMA2)
    conv_fwd<16, 32, 32, 4, 4, 2, 1, 56, 56, 28, 28, true>
        <<<dim3(784, 1), 256>>>(y1, w2, b2, bns + 0, bnsh + 0, y2);
    stats_partial<<<dim3(32, 64), 256>>>(y2, 32, 784, part);
    stats_final<<<32, 64>>>(part, 1.f / (512.f * 784.f), g2, be2, bns + 128, bnsh + 128);

    // layer 3: conv(32->64, 3x3, s1, p0) 28 -> 26  (HMMA implicit GEMM, 2 CTA/SM)
    {
        constexpr int INP_B = 12 * 28 * 40 * 2;
        constexpr int WTAP_B = 64 * 40 * 2;
        constexpr int S3 = 2 * INP_B + 4 * WTAP_B + (64 + 2 * 32) * 4;
        cudaFuncSetAttribute(conv_hmma<32, 64, 28, 28, 26, 26, 12, 2>,
                             cudaFuncAttributeMaxDynamicSharedMemorySize, S3);
        conv_hmma<32, 64, 28, 28, 26, 26, 12, 2>
            <<<dim3(4, 512), 256, S3>>>(y2, wt3h, wt3l, b3, bns + 128, bnsh + 128, y3);
    }
    stats_partial<<<dim3(64, 64), 256>>>(y3, 64, 676, part);
    stats_final<<<64, 64>>>(part, 1.f / (512.f * 676.f), g3, be3, bns + 256, bnsh + 256);

    // layer 4: conv(64->128, 3x3, s1, p0) 26 -> 24  (HMMA implicit GEMM)
    {
        constexpr int INP_B = 10 * 26 * 72 * 2;
        constexpr int WTAP_B = 128 * 72 * 2;
        constexpr int S4 = 2 * INP_B + 4 * WTAP_B + (128 + 2 * 64) * 4;
        cudaFuncSetAttribute(conv_hmma<64, 128, 26, 26, 24, 24, 10, 1>,
                             cudaFuncAttributeMaxDynamicSharedMemorySize, S4);
        conv_hmma<64, 128, 26, 26, 24, 24, 10, 1>
            <<<dim3(3, 512), 256, S4>>>(y3, wt4h, wt4l, b4, bns + 256, bnsh + 256, y4);
    }
    stats_partial<<<dim3(128, 64), 256>>>(y4, 128, 576, part);
    stats_final<<<128, 64>>>(part, 1.f / (512.f * 576.f), g4, be4, bns + 384, bnsh + 384);

    // GAP (+BN+ReLU fused) + feature normalize (+fp32 copy) + bf16 split
    gap_norm<<<512, 128>>>(y4, bns + 384, bnsh + 384, f32, fhi, flo);

    // arc weight row normalize + bf16 split
    wnorm_split<<<12500, 256>>>(arc, whi, wlo);

    // persistent split-bf16 HMMA cosine GEMM (scaled by 64), double-buffered B
    cudaFuncSetAttribute(arc_gemm, cudaFuncAttributeMaxDynamicSharedMemorySize, 6 * GT_BYTES);
    arc_gemm<<<dim3(4, NT_STRIDE), 256, 6 * GT_BYTES>>>(fhi, flo, whi, wlo, outp);

    // exact margin scatter (fp32 recompute; overwrites target entries)
    margin_kernel<<<128, 128>>>(outp, gt, f32, arc);
}